// round 6
// baseline (speedup 1.0000x reference)
#include <cuda_runtime.h>
#include <cstdint>

#define D_MODEL 1024
#define NHEAD   16
#define HDIM    64
#define BATCH   2
#define SEQ     2048
#define MROWS   (BATCH*SEQ)       // 4096
#define QKVDIM  (3*D_MODEL)       // 3072

// Scratch (no cudaMalloc allowed)
__device__ float g_qkv    [BATCH*SEQ*QKVDIM];   // 50 MB
__device__ float g_attn   [BATCH*SEQ*D_MODEL];  // 16 MB
__device__ float g_x32    [MROWS*D_MODEL];      // 16 MB  (x, tf32-rounded)
__device__ float g_wqkv32 [QKVDIM*D_MODEL];     // 12 MB
__device__ float g_wproj32[D_MODEL*D_MODEL];    //  4 MB

// ---------------------------------------------------------------------------
// helpers
// ---------------------------------------------------------------------------
static __device__ __forceinline__ uint32_t smem_u32(const void* p) {
    uint32_t a;
    asm("{ .reg .u64 t; cvta.to.shared.u64 t, %1; cvt.u32.u64 %0, t; }"
        : "=r"(a) : "l"(p));
    return a;
}
static __device__ __forceinline__ float f2tff(float x) {
    uint32_t t;
    asm("cvt.rna.tf32.f32 %0, %1;" : "=r"(t) : "f"(x));
    return __uint_as_float(t);
}
static __device__ __forceinline__ void mma8(
    float& c0, float& c1, float& c2, float& c3,
    uint32_t a0, uint32_t a1, uint32_t a2, uint32_t a3,
    uint32_t b0, uint32_t b1)
{
    asm volatile(
        "mma.sync.aligned.m16n8k8.row.col.f32.tf32.tf32.f32 "
        "{%0,%1,%2,%3}, {%4,%5,%6,%7}, {%8,%9}, {%0,%1,%2,%3};"
        : "+f"(c0), "+f"(c1), "+f"(c2), "+f"(c3)
        : "r"(a0), "r"(a1), "r"(a2), "r"(a3), "r"(b0), "r"(b1));
}
static __device__ __forceinline__ void ldmx4(
    uint32_t& r0, uint32_t& r1, uint32_t& r2, uint32_t& r3, uint32_t addr)
{
    asm volatile("ldmatrix.sync.aligned.m8n8.x4.shared.b16 {%0,%1,%2,%3}, [%4];"
                 : "=r"(r0), "=r"(r1), "=r"(r2), "=r"(r3) : "r"(addr));
}
static __device__ __forceinline__ void cpa16(uint32_t dst, const void* src) {
    asm volatile("cp.async.ca.shared.global [%0], [%1], 16;"
                 :: "r"(dst), "l"(src) : "memory");
}
static __device__ __forceinline__ void cpa_commit() {
    asm volatile("cp.async.commit_group;" ::: "memory");
}
static __device__ __forceinline__ void cpa_wait1() {
    asm volatile("cp.async.wait_group 1;" ::: "memory");
}

// ---------------------------------------------------------------------------
// pre-round f32 -> tf32 bit pattern (same cvt.rna as before, moved earlier)
// ---------------------------------------------------------------------------
__global__ void __launch_bounds__(256) round_tf32(
    const float4* __restrict__ in, float4* __restrict__ out, int n4)
{
    int i = blockIdx.x * 256 + threadIdx.x;
    if (i < n4) {
        float4 v = in[i];
        out[i] = make_float4(f2tff(v.x), f2tff(v.y), f2tff(v.z), f2tff(v.w));
    }
}

// ===========================================================================
// tf32 mma GEMM (TN), inputs pre-rounded to tf32:
//   C[m][n] = sum_k A[m*K+k] * B[n*K+k]
// BM=BN=128, BK=32. 256 thr, 8 warps (2m x 4n), warp tile 64x32.
// 3-stage cp.async pipeline; smem layout word m*32 + (k ^ ((m&7)<<2)),
// fragments via ldmatrix.x4 (b16 view). __launch_bounds__(256,2): 2 CTA/SM.
// ===========================================================================
#define GSTAGE_BYTES 32768
#define GEMM_SMEM    (3*GSTAGE_BYTES)    // 98304

static __device__ __forceinline__ int swz(int m, int k) {
    return m * 32 + (k ^ ((m & 7) << 2));
}

__global__ void __launch_bounds__(256, 2) gemm_tf32(
    const float* __restrict__ A, const float* __restrict__ B,
    float* __restrict__ C, int M, int N, int K)
{
    extern __shared__ float smg[];
    const uint32_t sbase = smem_u32(smg);

    const int tid  = threadIdx.x;
    const int wid  = tid >> 5;
    const int lane = tid & 31;
    const int g    = lane >> 2;
    const int ct   = lane & 3;
    const int wm   = wid & 1;       // warp m slice (x64)
    const int wn   = wid >> 1;      // warp n slice (x32)
    const int bm   = blockIdx.y * 128;
    const int bn   = blockIdx.x * 128;

    // ldmatrix lane mapping (b16 view of tf32 tiles)
    const int l8  = lane & 7;
    const int sel = lane >> 3;
    const uint32_t xv = (uint32_t)(l8 << 2);
    const int arow0 = wm * 64 + l8 + ((sel & 1) << 3);
    const int kca   = (sel >> 1) << 2;
    const int brow0 = wn * 32 + l8 + ((sel >> 1) << 3);
    const int kcb   = (sel & 1) << 2;

    uint32_t aoff[4], boff[2], kofa[4], kofb[4];
    #pragma unroll
    for (int mi = 0; mi < 4; mi++) aoff[mi] = (uint32_t)((arow0 + mi * 16) * 128);
    #pragma unroll
    for (int p = 0; p < 2; p++)  boff[p]  = 16384u + (uint32_t)((brow0 + p * 16) * 128);
    #pragma unroll
    for (int ks = 0; ks < 4; ks++) {
        kofa[ks] = (uint32_t)(((ks * 8 + kca) ^ (int)xv) << 2);
        kofb[ks] = (uint32_t)(((ks * 8 + kcb) ^ (int)xv) << 2);
    }

    // cp.async mapping: thread -> row (0..127), k-half (0/16); 4x16B each for A,B
    const int row = tid >> 1;
    const int kh  = (tid & 1) * 16;
    const float* Ag = A + (size_t)(bm + row) * K + kh;
    const float* Bg = B + (size_t)(bn + row) * K + kh;
    uint32_t dstw[4];
    #pragma unroll
    for (int i = 0; i < 4; i++) dstw[i] = (uint32_t)(swz(row, kh + i * 4) * 4);

    const int nkt = K / 32;

    float acc[4][4][4];
    #pragma unroll
    for (int i = 0; i < 4; i++)
        #pragma unroll
        for (int j = 0; j < 4; j++)
            #pragma unroll
            for (int e = 0; e < 4; e++) acc[i][j][e] = 0.f;

    // prologue: stages 0,1
    #pragma unroll
    for (int s = 0; s < 2; s++) {
        uint32_t st = sbase + (uint32_t)s * GSTAGE_BYTES;
        const float* Asrc = Ag + s * 32;
        const float* Bsrc = Bg + s * 32;
        #pragma unroll
        for (int i = 0; i < 4; i++) {
            cpa16(st + dstw[i],          Asrc + i * 4);
            cpa16(st + 16384u + dstw[i], Bsrc + i * 4);
        }
        cpa_commit();
    }

    int sc = 0;                       // stage of kt
    for (int kt = 0; kt < nkt; kt++) {
        cpa_wait1();
        __syncthreads();

        // issue kt+2 into the stage freed by kt-1 (barrier above orders it)
        if (kt + 2 < nkt) {
            int sn = sc + 2; if (sn >= 3) sn -= 3;
            uint32_t st = sbase + (uint32_t)sn * GSTAGE_BYTES;
            const float* Asrc = Ag + (kt + 2) * 32;
            const float* Bsrc = Bg + (kt + 2) * 32;
            #pragma unroll
            for (int i = 0; i < 4; i++) {
                cpa16(st + dstw[i],          Asrc + i * 4);
                cpa16(st + 16384u + dstw[i], Bsrc + i * 4);
            }
        }
        cpa_commit();   // (possibly empty) keeps wait_group counting uniform

        const uint32_t cbase = sbase + (uint32_t)sc * GSTAGE_BYTES;
        #pragma unroll
        for (int ks = 0; ks < 4; ks++) {
            uint32_t a[4][4], bb[2][4];
            #pragma unroll
            for (int mi = 0; mi < 4; mi++)
                ldmx4(a[mi][0], a[mi][1], a[mi][2], a[mi][3],
                      cbase + aoff[mi] + kofa[ks]);
            #pragma unroll
            for (int p = 0; p < 2; p++)
                ldmx4(bb[p][0], bb[p][1], bb[p][2], bb[p][3],
                      cbase + boff[p] + kofb[ks]);
            #pragma unroll
            for (int mi = 0; mi < 4; mi++)
                #pragma unroll
                for (int nt = 0; nt < 4; nt++)
                    mma8(acc[mi][nt][0], acc[mi][nt][1], acc[mi][nt][2], acc[mi][nt][3],
                         a[mi][0], a[mi][1], a[mi][2], a[mi][3],
                         bb[nt >> 1][(nt & 1) * 2], bb[nt >> 1][(nt & 1) * 2 + 1]);
        }
        sc++; if (sc >= 3) sc -= 3;
    }

    // epilogue: direct float2 stores
    #pragma unroll
    for (int mi = 0; mi < 4; mi++) {
        int r0 = bm + wm * 64 + mi * 16 + g;
        #pragma unroll
        for (int nt = 0; nt < 4; nt++) {
            int c0 = bn + wn * 32 + nt * 8 + 2 * ct;
            *(float2*)&C[(size_t)r0 * N + c0]       = make_float2(acc[mi][nt][0], acc[mi][nt][1]);
            *(float2*)&C[(size_t)(r0 + 8) * N + c0] = make_float2(acc[mi][nt][2], acc[mi][nt][3]);
        }
    }
}

// ===========================================================================
// Flash attention, tf32 mma + ldmatrix (round-5 version; epilogue now rounds
// output to tf32 so the projection GEMM can consume it directly).
// ===========================================================================
#define LDQ 68
#define LDK 68
#define LDV 72
#define LDP 68
#define QS_W   (128*LDQ)
#define KS_W   (64*LDK)
#define VS_W   (64*LDV)
#define PS_W   (128*LDP)
#define ATTN_SMEM ((QS_W+KS_W+VS_W+PS_W)*4)   // 105472 B

__global__ void __launch_bounds__(256) attn_mma(
    const float* __restrict__ qkv, float* __restrict__ attn_out)
{
    extern __shared__ float sm[];
    float* Qs = sm;
    float* Ks = Qs + QS_W;
    float* Vs = Ks + KS_W;
    float* Ps = Vs + VS_W;
    const uint32_t* Vu = (const uint32_t*)Vs;

    const int qt  = (int)gridDim.x - 1 - (int)blockIdx.x;
    const int h   = blockIdx.y;
    const int b   = blockIdx.z;
    const int tid = threadIdx.x;
    const int wid = tid >> 5;
    const int lane = tid & 31;
    const int g   = lane >> 2;
    const int ct  = lane & 3;
    const int q0  = qt * 128;
    const int rl  = wid * 16 + g;

    const int l8  = lane & 7;
    const int sel = lane >> 3;
    const int rowq = wid * 16 + l8 + ((sel & 1) << 3);
    const int kcq  = (sel >> 1) << 2;
    const int kck  = (sel & 1) << 2;
    const uint32_t q_base = smem_u32(Qs) + (uint32_t)((rowq * LDQ + kcq) * 4);
    const uint32_t p_base = smem_u32(Ps) + (uint32_t)((rowq * LDP + kcq) * 4);
    uint32_t k_base[4];
    #pragma unroll
    for (int j = 0; j < 4; j++) {
        int rowk = j * 16 + l8 + ((sel >> 1) << 3);
        k_base[j] = smem_u32(Ks) + (uint32_t)((rowk * LDK + kck) * 4);
    }

    const size_t rs = QKVDIM;
    const float* Qg = qkv + (size_t)b * SEQ * rs + h * HDIM;
    const float* Kg = Qg + D_MODEL;
    const float* Vg = Qg + 2 * D_MODEL;

    #pragma unroll
    for (int it = 0; it < 8; it++) {
        int idx = tid + it * 256;
        int rr  = idx >> 4;
        int d0  = (idx & 15) << 2;
        float4 q4 = *(const float4*)(Qg + (size_t)(q0 + rr) * rs + d0);
        *(float4*)&Qs[rr * LDQ + d0] = make_float4(
            f2tff(q4.x * 0.125f), f2tff(q4.y * 0.125f),
            f2tff(q4.z * 0.125f), f2tff(q4.w * 0.125f));
    }

    float m_lo = -1e30f, m_hi = -1e30f, l_lo = 0.f, l_hi = 0.f;
    float o[8][4];
    #pragma unroll
    for (int nt = 0; nt < 8; nt++)
        #pragma unroll
        for (int e = 0; e < 4; e++) o[nt][e] = 0.f;

    const int nkt = 2 * qt + 2;
    for (int kt = 0; kt < nkt; kt++) {
        const int k0 = kt * 64;
        __syncthreads();
        #pragma unroll
        for (int it = 0; it < 4; it++) {
            int idx = tid + it * 256;
            int rr  = idx >> 4;
            int d0  = (idx & 15) << 2;
            float4 k4 = *(const float4*)(Kg + (size_t)(k0 + rr) * rs + d0);
            *(float4*)&Ks[rr * LDK + d0] = make_float4(
                f2tff(k4.x), f2tff(k4.y), f2tff(k4.z), f2tff(k4.w));
            float4 v4 = *(const float4*)(Vg + (size_t)(k0 + rr) * rs + d0);
            *(float4*)&Vs[rr * LDV + d0] = make_float4(
                f2tff(v4.x), f2tff(v4.y), f2tff(v4.z), f2tff(v4.w));
        }
        __syncthreads();

        if (k0 > q0 + wid * 16 + 15) continue;

        float s[8][4];
        #pragma unroll
        for (int nt = 0; nt < 8; nt++)
            #pragma unroll
            for (int e = 0; e < 4; e++) s[nt][e] = 0.f;

        #pragma unroll
        for (int ks = 0; ks < 8; ks++) {
            uint32_t a0, a1, a2, a3;
            ldmx4(a0, a1, a2, a3, q_base + (uint32_t)(ks * 32));
            #pragma unroll
            for (int j = 0; j < 4; j++) {
                uint32_t b00, b01, b10, b11;
                ldmx4(b00, b01, b10, b11, k_base[j] + (uint32_t)(ks * 32));
                mma8(s[2*j][0], s[2*j][1], s[2*j][2], s[2*j][3],
                     a0, a1, a2, a3, b00, b01);
                mma8(s[2*j+1][0], s[2*j+1][1], s[2*j+1][2], s[2*j+1][3],
                     a0, a1, a2, a3, b10, b11);
            }
        }

        const int rglo = q0 + rl;
        const int rghi = rglo + 8;
        if (k0 + 63 > rglo) {
            #pragma unroll
            for (int nt = 0; nt < 8; nt++) {
                int key = k0 + nt * 8 + 2 * ct;
                if (key     > rglo) s[nt][0] = -1e30f;
                if (key + 1 > rglo) s[nt][1] = -1e30f;
                if (key     > rghi) s[nt][2] = -1e30f;
                if (key + 1 > rghi) s[nt][3] = -1e30f;
            }
        }

        float tlo = -1e30f, thi = -1e30f;
        #pragma unroll
        for (int nt = 0; nt < 8; nt++) {
            tlo = fmaxf(tlo, fmaxf(s[nt][0], s[nt][1]));
            thi = fmaxf(thi, fmaxf(s[nt][2], s[nt][3]));
        }
        tlo = fmaxf(tlo, __shfl_xor_sync(0xffffffffu, tlo, 1));
        tlo = fmaxf(tlo, __shfl_xor_sync(0xffffffffu, tlo, 2));
        thi = fmaxf(thi, __shfl_xor_sync(0xffffffffu, thi, 1));
        thi = fmaxf(thi, __shfl_xor_sync(0xffffffffu, thi, 2));

        float mn_lo = fmaxf(m_lo, tlo);
        float mn_hi = fmaxf(m_hi, thi);
        float al_lo = __expf(m_lo - mn_lo);
        float al_hi = __expf(m_hi - mn_hi);
        m_lo = mn_lo; m_hi = mn_hi;

        float ps_lo = 0.f, ps_hi = 0.f;
        #pragma unroll
        for (int nt = 0; nt < 8; nt++) {
            float p0 = __expf(s[nt][0] - mn_lo);
            float p1 = __expf(s[nt][1] - mn_lo);
            float p2 = __expf(s[nt][2] - mn_hi);
            float p3 = __expf(s[nt][3] - mn_hi);
            ps_lo += p0 + p1;
            ps_hi += p2 + p3;
            int col = nt * 8 + 2 * ct;
            *(float2*)&Ps[rl * LDP + col]       = make_float2(f2tff(p0), f2tff(p1));
            *(float2*)&Ps[(rl + 8) * LDP + col] = make_float2(f2tff(p2), f2tff(p3));
        }
        ps_lo += __shfl_xor_sync(0xffffffffu, ps_lo, 1);
        ps_lo += __shfl_xor_sync(0xffffffffu, ps_lo, 2);
        ps_hi += __shfl_xor_sync(0xffffffffu, ps_hi, 1);
        ps_hi += __shfl_xor_sync(0xffffffffu, ps_hi, 2);
        l_lo = l_lo * al_lo + ps_lo;
        l_hi = l_hi * al_hi + ps_hi;

        #pragma unroll
        for (int nt = 0; nt < 8; nt++) {
            o[nt][0] *= al_lo; o[nt][1] *= al_lo;
            o[nt][2] *= al_hi; o[nt][3] *= al_hi;
        }
        __syncwarp();

        #pragma unroll
        for (int ks = 0; ks < 8; ks++) {
            uint32_t a0, a1, a2, a3;
            ldmx4(a0, a1, a2, a3, p_base + (uint32_t)(ks * 32));
            #pragma unroll
            for (int nt = 0; nt < 8; nt++) {
                uint32_t b0 = Vu[(ks * 8 + ct) * LDV + nt * 8 + g];
                uint32_t b1 = Vu[(ks * 8 + ct + 4) * LDV + nt * 8 + g];
                mma8(o[nt][0], o[nt][1], o[nt][2], o[nt][3], a0, a1, a2, a3, b0, b1);
            }
        }
    }

    float inv_lo = 1.0f / l_lo;
    float inv_hi = 1.0f / l_hi;
    float* Og = attn_out + (size_t)(b * SEQ + q0) * D_MODEL + h * HDIM;
    #pragma unroll
    for (int nt = 0; nt < 8; nt++) {
        int col = nt * 8 + 2 * ct;
        *(float2*)&Og[(size_t)rl * D_MODEL + col] =
            make_float2(f2tff(o[nt][0] * inv_lo), f2tff(o[nt][1] * inv_lo));
        *(float2*)&Og[(size_t)(rl + 8) * D_MODEL + col] =
            make_float2(f2tff(o[nt][2] * inv_hi), f2tff(o[nt][3] * inv_hi));
    }
}

// ===========================================================================
extern "C" void kernel_launch(void* const* d_in, const int* in_sizes, int n_in,
                              void* d_out, int out_size)
{
    const float* x      = (const float*)d_in[0];
    const float* w_qkv  = (const float*)d_in[1];
    const float* w_proj = (const float*)d_in[2];
    float* out = (float*)d_out;

    float *qkv, *attn, *x32, *wq32, *wp32;
    cudaGetSymbolAddress((void**)&qkv,  g_qkv);
    cudaGetSymbolAddress((void**)&attn, g_attn);
    cudaGetSymbolAddress((void**)&x32,  g_x32);
    cudaGetSymbolAddress((void**)&wq32, g_wqkv32);
    cudaGetSymbolAddress((void**)&wp32, g_wproj32);

    cudaFuncSetAttribute(gemm_tf32,
                         cudaFuncAttributeMaxDynamicSharedMemorySize, GEMM_SMEM);
    cudaFuncSetAttribute(attn_mma,
                         cudaFuncAttributeMaxDynamicSharedMemorySize, ATTN_SMEM);

    // 0) pre-round inputs/weights to tf32 (identical cvt.rna, done once)
    int n4x = MROWS * D_MODEL / 4;
    int n4q = QKVDIM * D_MODEL / 4;
    int n4p = D_MODEL * D_MODEL / 4;
    round_tf32<<<(n4x + 255) / 256, 256>>>((const float4*)x,      (float4*)x32,  n4x);
    round_tf32<<<(n4q + 255) / 256, 256>>>((const float4*)w_qkv,  (float4*)wq32, n4q);
    round_tf32<<<(n4p + 255) / 256, 256>>>((const float4*)w_proj, (float4*)wp32, n4p);

    // 1) QKV projection
    dim3 g1(QKVDIM/128, MROWS/128);
    gemm_tf32<<<g1, 256, GEMM_SMEM>>>(x32, wq32, qkv, MROWS, QKVDIM, D_MODEL);

    // 2) causal flash attention (tf32 mma); epilogue rounds output to tf32
    dim3 g2(SEQ/128, NHEAD, BATCH);
    attn_mma<<<g2, 256, ATTN_SMEM>>>(qkv, attn);

    // 3) output projection
    dim3 g3(D_MODEL/128, MROWS/128);
    gemm_tf32<<<g3, 256, GEMM_SMEM>>>(attn, wp32, out, MROWS, D_MODEL, D_MODEL);
}

// round 7
// speedup vs baseline: 1.0067x; 1.0067x over previous
#include <cuda_runtime.h>
#include <cstdint>

#define D_MODEL 1024
#define NHEAD   16
#define HDIM    64
#define BATCH   2
#define SEQ     2048
#define MROWS   (BATCH*SEQ)       // 4096
#define QKVDIM  (3*D_MODEL)       // 3072

// Scratch (no cudaMalloc allowed)
__device__ float g_qkv    [BATCH*SEQ*QKVDIM];   // 50 MB
__device__ float g_attn   [BATCH*SEQ*D_MODEL];  // 16 MB
__device__ float g_x32    [MROWS*D_MODEL];      // 16 MB  (x, tf32-rounded)
__device__ float g_wqkv32 [QKVDIM*D_MODEL];     // 12 MB
__device__ float g_wproj32[D_MODEL*D_MODEL];    //  4 MB

// ---------------------------------------------------------------------------
// helpers
// ---------------------------------------------------------------------------
static __device__ __forceinline__ uint32_t smem_u32(const void* p) {
    uint32_t a;
    asm("{ .reg .u64 t; cvta.to.shared.u64 t, %1; cvt.u32.u64 %0, t; }"
        : "=r"(a) : "l"(p));
    return a;
}
static __device__ __forceinline__ float f2tff(float x) {
    uint32_t t;
    asm("cvt.rna.tf32.f32 %0, %1;" : "=r"(t) : "f"(x));
    return __uint_as_float(t);
}
static __device__ __forceinline__ void mma8(
    float& c0, float& c1, float& c2, float& c3,
    uint32_t a0, uint32_t a1, uint32_t a2, uint32_t a3,
    uint32_t b0, uint32_t b1)
{
    asm volatile(
        "mma.sync.aligned.m16n8k8.row.col.f32.tf32.tf32.f32 "
        "{%0,%1,%2,%3}, {%4,%5,%6,%7}, {%8,%9}, {%0,%1,%2,%3};"
        : "+f"(c0), "+f"(c1), "+f"(c2), "+f"(c3)
        : "r"(a0), "r"(a1), "r"(a2), "r"(a3), "r"(b0), "r"(b1));
}
static __device__ __forceinline__ void ldmx4(
    uint32_t& r0, uint32_t& r1, uint32_t& r2, uint32_t& r3, uint32_t addr)
{
    asm volatile("ldmatrix.sync.aligned.m8n8.x4.shared.b16 {%0,%1,%2,%3}, [%4];"
                 : "=r"(r0), "=r"(r1), "=r"(r2), "=r"(r3) : "r"(addr));
}
static __device__ __forceinline__ void cpa16(uint32_t dst, const void* src) {
    asm volatile("cp.async.ca.shared.global [%0], [%1], 16;"
                 :: "r"(dst), "l"(src) : "memory");
}
static __device__ __forceinline__ void cpa_commit() {
    asm volatile("cp.async.commit_group;" ::: "memory");
}
static __device__ __forceinline__ void cpa_wait1() {
    asm volatile("cp.async.wait_group 1;" ::: "memory");
}

// ---------------------------------------------------------------------------
// pre-round f32 -> tf32 bit pattern
// ---------------------------------------------------------------------------
__global__ void __launch_bounds__(256) round_tf32(
    const float4* __restrict__ in, float4* __restrict__ out, int n4)
{
    int i = blockIdx.x * 256 + threadIdx.x;
    if (i < n4) {
        float4 v = in[i];
        out[i] = make_float4(f2tff(v.x), f2tff(v.y), f2tff(v.z), f2tff(v.w));
    }
}

// ===========================================================================
// tf32 mma GEMM (TN), inputs pre-rounded to tf32:
//   C[m][n] = sum_k A[m*K+k] * B[n*K+k]
// CTA tile 256x128, BK=32. 256 thr, 8 warps (4m x 2n), warp tile 64x64.
// 3-stage cp.async; smem word layout m*32 + (k ^ ((m&7)<<2));
// fragments via ldmatrix.x4 (b16 view). 128 B smem traffic per mma.
// ===========================================================================
#define GA_BYTES     32768                    // A stage: 256 rows x 32 k x 4B
#define GSTAGE_BYTES 49152                    // + B stage: 128 x 32 x 4B
#define GEMM_SMEM    (3*GSTAGE_BYTES)         // 147456

static __device__ __forceinline__ int swz(int m, int k) {
    return m * 32 + (k ^ ((m & 7) << 2));
}

__global__ void __launch_bounds__(256, 1) gemm_tf32(
    const float* __restrict__ A, const float* __restrict__ B,
    float* __restrict__ C, int M, int N, int K)
{
    extern __shared__ float smg[];
    const uint32_t sbase = smem_u32(smg);

    const int tid  = threadIdx.x;
    const int wid  = tid >> 5;
    const int lane = tid & 31;
    const int g    = lane >> 2;
    const int ct   = lane & 3;
    const int wm   = wid & 3;       // warp m slice (x64), 4 slices
    const int wn   = wid >> 2;      // warp n slice (x64), 2 slices
    const int bm   = blockIdx.y * 256;
    const int bn   = blockIdx.x * 128;

    // ldmatrix lane mapping (b16 view of tf32 tiles)
    const int l8  = lane & 7;
    const int sel = lane >> 3;
    const uint32_t xv = (uint32_t)(l8 << 2);
    const int arow0 = wm * 64 + l8 + ((sel & 1) << 3);
    const int kca   = (sel >> 1) << 2;
    const int brow0 = wn * 64 + l8 + ((sel >> 1) << 3);
    const int kcb   = (sel & 1) << 2;

    uint32_t aoff[4], boff[4], kofa[4], kofb[4];
    #pragma unroll
    for (int mi = 0; mi < 4; mi++) aoff[mi] = (uint32_t)((arow0 + mi * 16) * 128);
    #pragma unroll
    for (int p = 0; p < 4; p++)  boff[p]  = (uint32_t)GA_BYTES + (uint32_t)((brow0 + p * 16) * 128);
    #pragma unroll
    for (int ks = 0; ks < 4; ks++) {
        kofa[ks] = (uint32_t)(((ks * 8 + kca) ^ (int)xv) << 2);
        kofb[ks] = (uint32_t)(((ks * 8 + kcb) ^ (int)xv) << 2);
    }

    // cp.async mapping:
    //  A: thread -> row tid (0..255), loads the whole 32-k slab (8 x 16B)
    //  B: thread -> row tid>>1 (0..127), k-half (tid&1)*16 (4 x 16B)
    const float* Ag = A + (size_t)(bm + tid) * K;
    const int rowb  = tid >> 1;
    const int khb   = (tid & 1) * 16;
    const float* Bg = B + (size_t)(bn + rowb) * K + khb;
    uint32_t dwa[8], dwb[4];
    #pragma unroll
    for (int i = 0; i < 8; i++) dwa[i] = (uint32_t)(swz(tid, i * 4) * 4);
    #pragma unroll
    for (int i = 0; i < 4; i++) dwb[i] = (uint32_t)GA_BYTES + (uint32_t)(swz(rowb, khb + i * 4) * 4);

    const int nkt = K / 32;

    float acc[4][8][4];
    #pragma unroll
    for (int i = 0; i < 4; i++)
        #pragma unroll
        for (int j = 0; j < 8; j++)
            #pragma unroll
            for (int e = 0; e < 4; e++) acc[i][j][e] = 0.f;

    // prologue: stages 0,1
    #pragma unroll
    for (int s = 0; s < 2; s++) {
        uint32_t st = sbase + (uint32_t)s * GSTAGE_BYTES;
        const float* Asrc = Ag + s * 32;
        const float* Bsrc = Bg + s * 32;
        #pragma unroll
        for (int i = 0; i < 8; i++) cpa16(st + dwa[i], Asrc + i * 4);
        #pragma unroll
        for (int i = 0; i < 4; i++) cpa16(st + dwb[i], Bsrc + i * 4);
        cpa_commit();
    }

    int sc = 0;
    for (int kt = 0; kt < nkt; kt++) {
        cpa_wait1();
        __syncthreads();

        if (kt + 2 < nkt) {
            int sn = sc + 2; if (sn >= 3) sn -= 3;
            uint32_t st = sbase + (uint32_t)sn * GSTAGE_BYTES;
            const float* Asrc = Ag + (kt + 2) * 32;
            const float* Bsrc = Bg + (kt + 2) * 32;
            #pragma unroll
            for (int i = 0; i < 8; i++) cpa16(st + dwa[i], Asrc + i * 4);
            #pragma unroll
            for (int i = 0; i < 4; i++) cpa16(st + dwb[i], Bsrc + i * 4);
        }
        cpa_commit();

        const uint32_t cbase = sbase + (uint32_t)sc * GSTAGE_BYTES;
        #pragma unroll
        for (int ks = 0; ks < 4; ks++) {
            uint32_t a[4][4], bb[4][4];
            #pragma unroll
            for (int mi = 0; mi < 4; mi++)
                ldmx4(a[mi][0], a[mi][1], a[mi][2], a[mi][3],
                      cbase + aoff[mi] + kofa[ks]);
            #pragma unroll
            for (int p = 0; p < 4; p++)
                ldmx4(bb[p][0], bb[p][1], bb[p][2], bb[p][3],
                      cbase + boff[p] + kofb[ks]);
            #pragma unroll
            for (int mi = 0; mi < 4; mi++)
                #pragma unroll
                for (int nt = 0; nt < 8; nt++)
                    mma8(acc[mi][nt][0], acc[mi][nt][1], acc[mi][nt][2], acc[mi][nt][3],
                         a[mi][0], a[mi][1], a[mi][2], a[mi][3],
                         bb[nt >> 1][(nt & 1) * 2], bb[nt >> 1][(nt & 1) * 2 + 1]);
        }
        sc++; if (sc >= 3) sc -= 3;
    }

    // epilogue: direct float2 stores
    #pragma unroll
    for (int mi = 0; mi < 4; mi++) {
        int r0 = bm + wm * 64 + mi * 16 + g;
        #pragma unroll
        for (int nt = 0; nt < 8; nt++) {
            int c0 = bn + wn * 64 + nt * 8 + 2 * ct;
            *(float2*)&C[(size_t)r0 * N + c0]       = make_float2(acc[mi][nt][0], acc[mi][nt][1]);
            *(float2*)&C[(size_t)(r0 + 8) * N + c0] = make_float2(acc[mi][nt][2], acc[mi][nt][3]);
        }
    }
}

// ===========================================================================
// Flash attention, tf32 mma + ldmatrix (unchanged from round 6).
// ===========================================================================
#define LDQ 68
#define LDK 68
#define LDV 72
#define LDP 68
#define QS_W   (128*LDQ)
#define KS_W   (64*LDK)
#define VS_W   (64*LDV)
#define PS_W   (128*LDP)
#define ATTN_SMEM ((QS_W+KS_W+VS_W+PS_W)*4)   // 105472 B

__global__ void __launch_bounds__(256) attn_mma(
    const float* __restrict__ qkv, float* __restrict__ attn_out)
{
    extern __shared__ float sm[];
    float* Qs = sm;
    float* Ks = Qs + QS_W;
    float* Vs = Ks + KS_W;
    float* Ps = Vs + VS_W;
    const uint32_t* Vu = (const uint32_t*)Vs;

    const int qt  = (int)gridDim.x - 1 - (int)blockIdx.x;
    const int h   = blockIdx.y;
    const int b   = blockIdx.z;
    const int tid = threadIdx.x;
    const int wid = tid >> 5;
    const int lane = tid & 31;
    const int g   = lane >> 2;
    const int ct  = lane & 3;
    const int q0  = qt * 128;
    const int rl  = wid * 16 + g;

    const int l8  = lane & 7;
    const int sel = lane >> 3;
    const int rowq = wid * 16 + l8 + ((sel & 1) << 3);
    const int kcq  = (sel >> 1) << 2;
    const int kck  = (sel & 1) << 2;
    const uint32_t q_base = smem_u32(Qs) + (uint32_t)((rowq * LDQ + kcq) * 4);
    const uint32_t p_base = smem_u32(Ps) + (uint32_t)((rowq * LDP + kcq) * 4);
    uint32_t k_base[4];
    #pragma unroll
    for (int j = 0; j < 4; j++) {
        int rowk = j * 16 + l8 + ((sel >> 1) << 3);
        k_base[j] = smem_u32(Ks) + (uint32_t)((rowk * LDK + kck) * 4);
    }

    const size_t rs = QKVDIM;
    const float* Qg = qkv + (size_t)b * SEQ * rs + h * HDIM;
    const float* Kg = Qg + D_MODEL;
    const float* Vg = Qg + 2 * D_MODEL;

    #pragma unroll
    for (int it = 0; it < 8; it++) {
        int idx = tid + it * 256;
        int rr  = idx >> 4;
        int d0  = (idx & 15) << 2;
        float4 q4 = *(const float4*)(Qg + (size_t)(q0 + rr) * rs + d0);
        *(float4*)&Qs[rr * LDQ + d0] = make_float4(
            f2tff(q4.x * 0.125f), f2tff(q4.y * 0.125f),
            f2tff(q4.z * 0.125f), f2tff(q4.w * 0.125f));
    }

    float m_lo = -1e30f, m_hi = -1e30f, l_lo = 0.f, l_hi = 0.f;
    float o[8][4];
    #pragma unroll
    for (int nt = 0; nt < 8; nt++)
        #pragma unroll
        for (int e = 0; e < 4; e++) o[nt][e] = 0.f;

    const int nkt = 2 * qt + 2;
    for (int kt = 0; kt < nkt; kt++) {
        const int k0 = kt * 64;
        __syncthreads();
        #pragma unroll
        for (int it = 0; it < 4; it++) {
            int idx = tid + it * 256;
            int rr  = idx >> 4;
            int d0  = (idx & 15) << 2;
            float4 k4 = *(const float4*)(Kg + (size_t)(k0 + rr) * rs + d0);
            *(float4*)&Ks[rr * LDK + d0] = make_float4(
                f2tff(k4.x), f2tff(k4.y), f2tff(k4.z), f2tff(k4.w));
            float4 v4 = *(const float4*)(Vg + (size_t)(k0 + rr) * rs + d0);
            *(float4*)&Vs[rr * LDV + d0] = make_float4(
                f2tff(v4.x), f2tff(v4.y), f2tff(v4.z), f2tff(v4.w));
        }
        __syncthreads();

        if (k0 > q0 + wid * 16 + 15) continue;

        float s[8][4];
        #pragma unroll
        for (int nt = 0; nt < 8; nt++)
            #pragma unroll
            for (int e = 0; e < 4; e++) s[nt][e] = 0.f;

        #pragma unroll
        for (int ks = 0; ks < 8; ks++) {
            uint32_t a0, a1, a2, a3;
            ldmx4(a0, a1, a2, a3, q_base + (uint32_t)(ks * 32));
            #pragma unroll
            for (int j = 0; j < 4; j++) {
                uint32_t b00, b01, b10, b11;
                ldmx4(b00, b01, b10, b11, k_base[j] + (uint32_t)(ks * 32));
                mma8(s[2*j][0], s[2*j][1], s[2*j][2], s[2*j][3],
                     a0, a1, a2, a3, b00, b01);
                mma8(s[2*j+1][0], s[2*j+1][1], s[2*j+1][2], s[2*j+1][3],
                     a0, a1, a2, a3, b10, b11);
            }
        }

        const int rglo = q0 + rl;
        const int rghi = rglo + 8;
        if (k0 + 63 > rglo) {
            #pragma unroll
            for (int nt = 0; nt < 8; nt++) {
                int key = k0 + nt * 8 + 2 * ct;
                if (key     > rglo) s[nt][0] = -1e30f;
                if (key + 1 > rglo) s[nt][1] = -1e30f;
                if (key     > rghi) s[nt][2] = -1e30f;
                if (key + 1 > rghi) s[nt][3] = -1e30f;
            }
        }

        float tlo = -1e30f, thi = -1e30f;
        #pragma unroll
        for (int nt = 0; nt < 8; nt++) {
            tlo = fmaxf(tlo, fmaxf(s[nt][0], s[nt][1]));
            thi = fmaxf(thi, fmaxf(s[nt][2], s[nt][3]));
        }
        tlo = fmaxf(tlo, __shfl_xor_sync(0xffffffffu, tlo, 1));
        tlo = fmaxf(tlo, __shfl_xor_sync(0xffffffffu, tlo, 2));
        thi = fmaxf(thi, __shfl_xor_sync(0xffffffffu, thi, 1));
        thi = fmaxf(thi, __shfl_xor_sync(0xffffffffu, thi, 2));

        float mn_lo = fmaxf(m_lo, tlo);
        float mn_hi = fmaxf(m_hi, thi);
        float al_lo = __expf(m_lo - mn_lo);
        float al_hi = __expf(m_hi - mn_hi);
        m_lo = mn_lo; m_hi = mn_hi;

        float ps_lo = 0.f, ps_hi = 0.f;
        #pragma unroll
        for (int nt = 0; nt < 8; nt++) {
            float p0 = __expf(s[nt][0] - mn_lo);
            float p1 = __expf(s[nt][1] - mn_lo);
            float p2 = __expf(s[nt][2] - mn_hi);
            float p3 = __expf(s[nt][3] - mn_hi);
            ps_lo += p0 + p1;
            ps_hi += p2 + p3;
            int col = nt * 8 + 2 * ct;
            *(float2*)&Ps[rl * LDP + col]       = make_float2(f2tff(p0), f2tff(p1));
            *(float2*)&Ps[(rl + 8) * LDP + col] = make_float2(f2tff(p2), f2tff(p3));
        }
        ps_lo += __shfl_xor_sync(0xffffffffu, ps_lo, 1);
        ps_lo += __shfl_xor_sync(0xffffffffu, ps_lo, 2);
        ps_hi += __shfl_xor_sync(0xffffffffu, ps_hi, 1);
        ps_hi += __shfl_xor_sync(0xffffffffu, ps_hi, 2);
        l_lo = l_lo * al_lo + ps_lo;
        l_hi = l_hi * al_hi + ps_hi;

        #pragma unroll
        for (int nt = 0; nt < 8; nt++) {
            o[nt][0] *= al_lo; o[nt][1] *= al_lo;
            o[nt][2] *= al_hi; o[nt][3] *= al_hi;
        }
        __syncwarp();

        #pragma unroll
        for (int ks = 0; ks < 8; ks++) {
            uint32_t a0, a1, a2, a3;
            ldmx4(a0, a1, a2, a3, p_base + (uint32_t)(ks * 32));
            #pragma unroll
            for (int nt = 0; nt < 8; nt++) {
                uint32_t b0 = Vu[(ks * 8 + ct) * LDV + nt * 8 + g];
                uint32_t b1 = Vu[(ks * 8 + ct + 4) * LDV + nt * 8 + g];
                mma8(o[nt][0], o[nt][1], o[nt][2], o[nt][3], a0, a1, a2, a3, b0, b1);
            }
        }
    }

    float inv_lo = 1.0f / l_lo;
    float inv_hi = 1.0f / l_hi;
    float* Og = attn_out + (size_t)(b * SEQ + q0) * D_MODEL + h * HDIM;
    #pragma unroll
    for (int nt = 0; nt < 8; nt++) {
        int col = nt * 8 + 2 * ct;
        *(float2*)&Og[(size_t)rl * D_MODEL + col] =
            make_float2(f2tff(o[nt][0] * inv_lo), f2tff(o[nt][1] * inv_lo));
        *(float2*)&Og[(size_t)(rl + 8) * D_MODEL + col] =
            make_float2(f2tff(o[nt][2] * inv_hi), f2tff(o[nt][3] * inv_hi));
    }
}

// ===========================================================================
extern "C" void kernel_launch(void* const* d_in, const int* in_sizes, int n_in,
                              void* d_out, int out_size)
{
    const float* x      = (const float*)d_in[0];
    const float* w_qkv  = (const float*)d_in[1];
    const float* w_proj = (const float*)d_in[2];
    float* out = (float*)d_out;

    float *qkv, *attn, *x32, *wq32, *wp32;
    cudaGetSymbolAddress((void**)&qkv,  g_qkv);
    cudaGetSymbolAddress((void**)&attn, g_attn);
    cudaGetSymbolAddress((void**)&x32,  g_x32);
    cudaGetSymbolAddress((void**)&wq32, g_wqkv32);
    cudaGetSymbolAddress((void**)&wp32, g_wproj32);

    cudaFuncSetAttribute(gemm_tf32,
                         cudaFuncAttributeMaxDynamicSharedMemorySize, GEMM_SMEM);
    cudaFuncSetAttribute(attn_mma,
                         cudaFuncAttributeMaxDynamicSharedMemorySize, ATTN_SMEM);

    // 0) pre-round inputs/weights to tf32
    int n4x = MROWS * D_MODEL / 4;
    int n4q = QKVDIM * D_MODEL / 4;
    int n4p = D_MODEL * D_MODEL / 4;
    round_tf32<<<(n4x + 255) / 256, 256>>>((const float4*)x,      (float4*)x32,  n4x);
    round_tf32<<<(n4q + 255) / 256, 256>>>((const float4*)w_qkv,  (float4*)wq32, n4q);
    round_tf32<<<(n4p + 255) / 256, 256>>>((const float4*)w_proj, (float4*)wp32, n4p);

    // 1) QKV projection (CTA tile 256x128)
    dim3 g1(QKVDIM/128, MROWS/256);
    gemm_tf32<<<g1, 256, GEMM_SMEM>>>(x32, wq32, qkv, MROWS, QKVDIM, D_MODEL);

    // 2) causal flash attention
    dim3 g2(SEQ/128, NHEAD, BATCH);
    attn_mma<<<g2, 256, ATTN_SMEM>>>(qkv, attn);

    // 3) output projection
    dim3 g3(D_MODEL/128, MROWS/256);
    gemm_tf32<<<g3, 256, GEMM_SMEM>>>(attn, wp32, out, MROWS, D_MODEL, D_MODEL);
}

// round 8
// speedup vs baseline: 1.7963x; 1.7844x over previous
#include <cuda_runtime.h>
#include <cuda_fp16.h>
#include <cstdint>

#define D_MODEL 1024
#define NHEAD   16
#define HDIM    64
#define BATCH   2
#define SEQ     2048
#define MROWS   (BATCH*SEQ)       // 4096
#define QKVDIM  (3*D_MODEL)       // 3072

// Scratch (no cudaMalloc allowed)
__device__ __half g_qkvh [BATCH*SEQ*QKVDIM];   // 25 MB
__device__ __half g_attnh[BATCH*SEQ*D_MODEL];  //  8 MB
__device__ __half g_xh   [MROWS*D_MODEL];      //  8 MB
__device__ __half g_wqh  [QKVDIM*D_MODEL];     //  6 MB
__device__ __half g_wph  [D_MODEL*D_MODEL];    //  2 MB

// ---------------------------------------------------------------------------
// helpers
// ---------------------------------------------------------------------------
static __device__ __forceinline__ uint32_t smem_u32(const void* p) {
    uint32_t a;
    asm("{ .reg .u64 t; cvta.to.shared.u64 t, %1; cvt.u32.u64 %0, t; }"
        : "=r"(a) : "l"(p));
    return a;
}
// D(16x8) += A(16x16) * B(16x8), fp16 inputs, fp32 accum
static __device__ __forceinline__ void mma16(
    float& c0, float& c1, float& c2, float& c3,
    uint32_t a0, uint32_t a1, uint32_t a2, uint32_t a3,
    uint32_t b0, uint32_t b1)
{
    asm volatile(
        "mma.sync.aligned.m16n8k16.row.col.f32.f16.f16.f32 "
        "{%0,%1,%2,%3}, {%4,%5,%6,%7}, {%8,%9}, {%0,%1,%2,%3};"
        : "+f"(c0), "+f"(c1), "+f"(c2), "+f"(c3)
        : "r"(a0), "r"(a1), "r"(a2), "r"(a3), "r"(b0), "r"(b1));
}
static __device__ __forceinline__ void ldmx4(
    uint32_t& r0, uint32_t& r1, uint32_t& r2, uint32_t& r3, uint32_t addr)
{
    asm volatile("ldmatrix.sync.aligned.m8n8.x4.shared.b16 {%0,%1,%2,%3}, [%4];"
                 : "=r"(r0), "=r"(r1), "=r"(r2), "=r"(r3) : "r"(addr));
}
static __device__ __forceinline__ void ldmx4t(
    uint32_t& r0, uint32_t& r1, uint32_t& r2, uint32_t& r3, uint32_t addr)
{
    asm volatile("ldmatrix.sync.aligned.m8n8.x4.trans.shared.b16 {%0,%1,%2,%3}, [%4];"
                 : "=r"(r0), "=r"(r1), "=r"(r2), "=r"(r3) : "r"(addr));
}
static __device__ __forceinline__ void cpa16(uint32_t dst, const void* src) {
    asm volatile("cp.async.ca.shared.global [%0], [%1], 16;"
                 :: "r"(dst), "l"(src) : "memory");
}
static __device__ __forceinline__ void cpa_commit() {
    asm volatile("cp.async.commit_group;" ::: "memory");
}
static __device__ __forceinline__ void cpa_wait1() {
    asm volatile("cp.async.wait_group 1;" ::: "memory");
}
static __device__ __forceinline__ void st2h(__half* C, size_t off, float a, float b) {
    *(__half2*)(C + off) = __floats2half2_rn(a, b);
}
static __device__ __forceinline__ void st2h(float* C, size_t off, float a, float b) {
    *(float2*)(C + off) = make_float2(a, b);
}

// ---------------------------------------------------------------------------
// f32 -> f16 conversion
// ---------------------------------------------------------------------------
__global__ void __launch_bounds__(256) f2h(
    const float4* __restrict__ in, __half2* __restrict__ out, int n4)
{
    int i = blockIdx.x * 256 + threadIdx.x;
    if (i < n4) {
        float4 v = in[i];
        out[2 * i]     = __floats2half2_rn(v.x, v.y);
        out[2 * i + 1] = __floats2half2_rn(v.z, v.w);
    }
}

// ===========================================================================
// fp16 mma GEMM (TN): C[m][n] = sum_k A[m*K+k]*B[n*K+k], fp32 accumulate.
// CTA tile 128x128, BK=64 halves (128B rows). 256 thr, 8 warps (2m x 4n),
// warp tile 64x32. Rows swizzled: 16B chunk c at c ^ (row&7).
// 3-stage cp.async. All fragments via ldmatrix.x4.
// ===========================================================================
#define HSTAGE    32768          // A 16KB + B 16KB
#define GEMM_SMEM (3*HSTAGE)     // 98304

template<typename OutT>
__global__ void __launch_bounds__(256) gemm_f16(
    const __half* __restrict__ A, const __half* __restrict__ B,
    OutT* __restrict__ C, int M, int N, int K)
{
    extern __shared__ char smh[];
    const uint32_t sbase = smem_u32(smh);

    const int tid  = threadIdx.x;
    const int wid  = tid >> 5;
    const int lane = tid & 31;
    const int g    = lane >> 2;
    const int ct   = lane & 3;
    const int wm   = wid & 1;       // m slice (x64)
    const int wn   = wid >> 1;      // n slice (x32)
    const int bm   = blockIdx.y * 128;
    const int bn   = blockIdx.x * 128;

    const int l8 = lane & 7;
    const int h1 = (lane >> 3) & 1;
    const int h2 = lane >> 4;

    // fragment base rows (A-type: rows use h1; B-type: rows use h2)
    uint32_t arow[4], a7[4], brow[2], b7[2];
    #pragma unroll
    for (int mi = 0; mi < 4; mi++) {
        int r = wm * 64 + mi * 16 + l8 + h1 * 8;
        arow[mi] = (uint32_t)(r * 128);
        a7[mi]   = (uint32_t)(r & 7);
    }
    #pragma unroll
    for (int p = 0; p < 2; p++) {
        int r = wn * 32 + p * 16 + l8 + h2 * 8;
        brow[p] = 16384u + (uint32_t)(r * 128);
        b7[p]   = (uint32_t)(r & 7);
    }

    // cp.async mapping: thread -> row tid>>1 (0..127), 4 chunks at (tid&1)*4
    const int crow = tid >> 1;
    const int cc0  = (tid & 1) * 4;
    const __half* Ag = A + (size_t)(bm + crow) * K;
    const __half* Bg = B + (size_t)(bn + crow) * K;
    uint32_t dwa[4], dwb[4];
    #pragma unroll
    for (int i = 0; i < 4; i++) {
        uint32_t sw = (uint32_t)(((cc0 + i) ^ (crow & 7)) * 16);
        dwa[i] = (uint32_t)(crow * 128) + sw;
        dwb[i] = 16384u + (uint32_t)(crow * 128) + sw;
    }

    const int nkt = K / 64;

    float acc[4][4][4];
    #pragma unroll
    for (int i = 0; i < 4; i++)
        #pragma unroll
        for (int j = 0; j < 4; j++)
            #pragma unroll
            for (int e = 0; e < 4; e++) acc[i][j][e] = 0.f;

    // prologue: stages 0,1
    #pragma unroll
    for (int s = 0; s < 2; s++) {
        uint32_t st = sbase + (uint32_t)s * HSTAGE;
        #pragma unroll
        for (int i = 0; i < 4; i++) {
            cpa16(st + dwa[i], Ag + s * 64 + (cc0 + i) * 8);
            cpa16(st + dwb[i], Bg + s * 64 + (cc0 + i) * 8);
        }
        cpa_commit();
    }

    int sc = 0;
    for (int kt = 0; kt < nkt; kt++) {
        cpa_wait1();
        __syncthreads();

        if (kt + 2 < nkt) {
            int sn = sc + 2; if (sn >= 3) sn -= 3;
            uint32_t st = sbase + (uint32_t)sn * HSTAGE;
            #pragma unroll
            for (int i = 0; i < 4; i++) {
                cpa16(st + dwa[i], Ag + (kt + 2) * 64 + (cc0 + i) * 8);
                cpa16(st + dwb[i], Bg + (kt + 2) * 64 + (cc0 + i) * 8);
            }
        }
        cpa_commit();

        const uint32_t cbase = sbase + (uint32_t)sc * HSTAGE;
        #pragma unroll
        for (int ks = 0; ks < 4; ks++) {
            uint32_t a[4][4], bb[2][4];
            #pragma unroll
            for (int mi = 0; mi < 4; mi++)
                ldmx4(a[mi][0], a[mi][1], a[mi][2], a[mi][3],
                      cbase + arow[mi] + ((((uint32_t)(ks * 2 + h2)) ^ a7[mi]) << 4));
            #pragma unroll
            for (int p = 0; p < 2; p++)
                ldmx4(bb[p][0], bb[p][1], bb[p][2], bb[p][3],
                      cbase + brow[p] + ((((uint32_t)(ks * 2 + h1)) ^ b7[p]) << 4));
            #pragma unroll
            for (int mi = 0; mi < 4; mi++)
                #pragma unroll
                for (int nt = 0; nt < 4; nt++)
                    mma16(acc[mi][nt][0], acc[mi][nt][1], acc[mi][nt][2], acc[mi][nt][3],
                          a[mi][0], a[mi][1], a[mi][2], a[mi][3],
                          bb[nt >> 1][(nt & 1) * 2], bb[nt >> 1][(nt & 1) * 2 + 1]);
        }
        sc++; if (sc >= 3) sc -= 3;
    }

    #pragma unroll
    for (int mi = 0; mi < 4; mi++) {
        int r0 = bm + wm * 64 + mi * 16 + g;
        #pragma unroll
        for (int nt = 0; nt < 4; nt++) {
            int c0 = bn + wn * 32 + nt * 8 + 2 * ct;
            st2h(C, (size_t)r0 * N + c0,       acc[mi][nt][0], acc[mi][nt][1]);
            st2h(C, (size_t)(r0 + 8) * N + c0, acc[mi][nt][2], acc[mi][nt][3]);
        }
    }
}

// ===========================================================================
// Flash attention, fp16 mma. Q tile 128, K/V tile 64, d=64.
// 8 warps, warp w owns rows [w*16, w*16+16). All smem rows = 64 halves =
// 128B, chunk-swizzled c ^ (row&7). V via ldmatrix.trans. Softmax in fp32;
// scale 0.125 applied to S post-mma.
// ===========================================================================
#define AQ_OFF 0
#define AK_OFF 16384
#define AV_OFF 24576
#define AP_OFF 32768
#define ATTN_SMEM 49152

__global__ void __launch_bounds__(256) attn_f16(
    const __half* __restrict__ qkv, __half* __restrict__ attn_out)
{
    extern __shared__ char smh[];
    const uint32_t sb = smem_u32(smh);

    const int qt  = (int)gridDim.x - 1 - (int)blockIdx.x;  // heavy blocks first
    const int h   = blockIdx.y;
    const int b   = blockIdx.z;
    const int tid = threadIdx.x;
    const int wid = tid >> 5;
    const int lane = tid & 31;
    const int g   = lane >> 2;
    const int ct  = lane & 3;
    const int q0  = qt * 128;
    const int rl  = wid * 16 + g;

    const int l8 = lane & 7;
    const int h1 = (lane >> 3) & 1;
    const int h2 = lane >> 4;

    // A-type rows (Q and P share mapping)
    const int arow = wid * 16 + l8 + h1 * 8;
    const uint32_t qbase = sb + AQ_OFF + (uint32_t)(arow * 128);
    const uint32_t pbase = sb + AP_OFF + (uint32_t)(arow * 128);
    const uint32_t a7 = (uint32_t)(arow & 7);
    // K rows (B-type)
    uint32_t krow[4], k7[4];
    #pragma unroll
    for (int p = 0; p < 4; p++) {
        int r = p * 16 + l8 + h2 * 8;
        krow[p] = sb + AK_OFF + (uint32_t)(r * 128);
        k7[p]   = (uint32_t)(r & 7);
    }
    // V rows (trans; rows move with ks)
    const int vr0 = l8 + h1 * 8;

    const size_t rs = QKVDIM;
    const __half* Qg = qkv + (size_t)b * SEQ * rs + h * HDIM;
    const __half* Kg = Qg + D_MODEL;
    const __half* Vg = Qg + 2 * D_MODEL;

    // load Q tile: 128 rows x 8 chunks of 16B
    #pragma unroll
    for (int it = 0; it < 4; it++) {
        int idx = tid + it * 256;
        int rr  = idx >> 3;
        int c   = idx & 7;
        uint4 v = *(const uint4*)(Qg + (size_t)(q0 + rr) * rs + c * 8);
        *(uint4*)(smh + AQ_OFF + rr * 128 + ((c ^ (rr & 7)) * 16)) = v;
    }

    float m_lo = -1e30f, m_hi = -1e30f, l_lo = 0.f, l_hi = 0.f;
    float o[8][4];
    #pragma unroll
    for (int nt = 0; nt < 8; nt++)
        #pragma unroll
        for (int e = 0; e < 4; e++) o[nt][e] = 0.f;

    const int nkt = 2 * qt + 2;
    for (int kt = 0; kt < nkt; kt++) {
        const int k0 = kt * 64;
        __syncthreads();
        #pragma unroll
        for (int it = 0; it < 2; it++) {
            int idx = tid + it * 256;
            int rr  = idx >> 3;
            int c   = idx & 7;
            uint32_t sw = (uint32_t)(rr * 128 + ((c ^ (rr & 7)) * 16));
            uint4 kv = *(const uint4*)(Kg + (size_t)(k0 + rr) * rs + c * 8);
            *(uint4*)(smh + AK_OFF + sw) = kv;
            uint4 vv = *(const uint4*)(Vg + (size_t)(k0 + rr) * rs + c * 8);
            *(uint4*)(smh + AV_OFF + sw) = vv;
        }
        __syncthreads();

        if (k0 > q0 + wid * 16 + 15) continue;

        // ---- S = Q K^T (k = 64, 4 ks-steps of k16) ----
        float s[8][4];
        #pragma unroll
        for (int nt = 0; nt < 8; nt++)
            #pragma unroll
            for (int e = 0; e < 4; e++) s[nt][e] = 0.f;

        #pragma unroll
        for (int ks = 0; ks < 4; ks++) {
            uint32_t a0, a1, a2, a3;
            ldmx4(a0, a1, a2, a3, qbase + ((((uint32_t)(ks * 2 + h2)) ^ a7) << 4));
            #pragma unroll
            for (int p = 0; p < 4; p++) {
                uint32_t b0, b1, b2, b3;
                ldmx4(b0, b1, b2, b3, krow[p] + ((((uint32_t)(ks * 2 + h1)) ^ k7[p]) << 4));
                mma16(s[2*p][0], s[2*p][1], s[2*p][2], s[2*p][3],
                      a0, a1, a2, a3, b0, b1);
                mma16(s[2*p+1][0], s[2*p+1][1], s[2*p+1][2], s[2*p+1][3],
                      a0, a1, a2, a3, b2, b3);
            }
        }
        #pragma unroll
        for (int nt = 0; nt < 8; nt++)
            #pragma unroll
            for (int e = 0; e < 4; e++) s[nt][e] *= 0.125f;

        // ---- causal mask ----
        const int rglo = q0 + rl;
        const int rghi = rglo + 8;
        if (k0 + 63 > rglo) {
            #pragma unroll
            for (int nt = 0; nt < 8; nt++) {
                int key = k0 + nt * 8 + 2 * ct;
                if (key     > rglo) s[nt][0] = -1e30f;
                if (key + 1 > rglo) s[nt][1] = -1e30f;
                if (key     > rghi) s[nt][2] = -1e30f;
                if (key + 1 > rghi) s[nt][3] = -1e30f;
            }
        }

        // ---- online softmax (quad reduce) ----
        float tlo = -1e30f, thi = -1e30f;
        #pragma unroll
        for (int nt = 0; nt < 8; nt++) {
            tlo = fmaxf(tlo, fmaxf(s[nt][0], s[nt][1]));
            thi = fmaxf(thi, fmaxf(s[nt][2], s[nt][3]));
        }
        tlo = fmaxf(tlo, __shfl_xor_sync(0xffffffffu, tlo, 1));
        tlo = fmaxf(tlo, __shfl_xor_sync(0xffffffffu, tlo, 2));
        thi = fmaxf(thi, __shfl_xor_sync(0xffffffffu, thi, 1));
        thi = fmaxf(thi, __shfl_xor_sync(0xffffffffu, thi, 2));

        float mn_lo = fmaxf(m_lo, tlo);
        float mn_hi = fmaxf(m_hi, thi);
        float al_lo = __expf(m_lo - mn_lo);
        float al_hi = __expf(m_hi - mn_hi);
        m_lo = mn_lo; m_hi = mn_hi;

        float ps_lo = 0.f, ps_hi = 0.f;
        #pragma unroll
        for (int nt = 0; nt < 8; nt++) {
            float p0 = __expf(s[nt][0] - mn_lo);
            float p1 = __expf(s[nt][1] - mn_lo);
            float p2 = __expf(s[nt][2] - mn_hi);
            float p3 = __expf(s[nt][3] - mn_hi);
            ps_lo += p0 + p1;
            ps_hi += p2 + p3;
            // store P as half2 into swizzled Ph: row rl(+8), cols nt*8+2ct
            uint32_t swl = (uint32_t)(rl * 128 + (((nt) ^ (rl & 7)) * 16) + 4 * ct);
            uint32_t swh = (uint32_t)((rl + 8) * 128 + (((nt) ^ ((rl + 8) & 7)) * 16) + 4 * ct);
            *(__half2*)(smh + AP_OFF + swl) = __floats2half2_rn(p0, p1);
            *(__half2*)(smh + AP_OFF + swh) = __floats2half2_rn(p2, p3);
        }
        ps_lo += __shfl_xor_sync(0xffffffffu, ps_lo, 1);
        ps_lo += __shfl_xor_sync(0xffffffffu, ps_lo, 2);
        ps_hi += __shfl_xor_sync(0xffffffffu, ps_hi, 1);
        ps_hi += __shfl_xor_sync(0xffffffffu, ps_hi, 2);
        l_lo = l_lo * al_lo + ps_lo;
        l_hi = l_hi * al_hi + ps_hi;

        #pragma unroll
        for (int nt = 0; nt < 8; nt++) {
            o[nt][0] *= al_lo; o[nt][1] *= al_lo;
            o[nt][2] *= al_hi; o[nt][3] *= al_hi;
        }
        __syncwarp();

        // ---- O += P V (k = j = 64, 4 ks-steps; V via ldmatrix.trans) ----
        #pragma unroll
        for (int ks = 0; ks < 4; ks++) {
            uint32_t a0, a1, a2, a3;
            ldmx4(a0, a1, a2, a3, pbase + ((((uint32_t)(ks * 2 + h2)) ^ a7) << 4));
            int vrow = ks * 16 + vr0;
            uint32_t vbase = sb + AV_OFF + (uint32_t)(vrow * 128);
            uint32_t v7 = (uint32_t)(vrow & 7);
            #pragma unroll
            for (int pn = 0; pn < 4; pn++) {
                uint32_t b0, b1, b2, b3;
                ldmx4t(b0, b1, b2, b3, vbase + ((((uint32_t)(pn * 2 + h2 == h2 ? pn * 2 + h2 : pn * 2 + h2)) ^ v7) << 4));
                mma16(o[2*pn][0], o[2*pn][1], o[2*pn][2], o[2*pn][3],
                      a0, a1, a2, a3, b0, b1);
                mma16(o[2*pn+1][0], o[2*pn+1][1], o[2*pn+1][2], o[2*pn+1][3],
                      a0, a1, a2, a3, b2, b3);
            }
        }
    }

    float inv_lo = 1.0f / l_lo;
    float inv_hi = 1.0f / l_hi;
    __half* Og = attn_out + (size_t)(b * SEQ + q0) * D_MODEL + h * HDIM;
    #pragma unroll
    for (int nt = 0; nt < 8; nt++) {
        int col = nt * 8 + 2 * ct;
        *(__half2*)&Og[(size_t)rl * D_MODEL + col] =
            __floats2half2_rn(o[nt][0] * inv_lo, o[nt][1] * inv_lo);
        *(__half2*)&Og[(size_t)(rl + 8) * D_MODEL + col] =
            __floats2half2_rn(o[nt][2] * inv_hi, o[nt][3] * inv_hi);
    }
}

// ===========================================================================
extern "C" void kernel_launch(void* const* d_in, const int* in_sizes, int n_in,
                              void* d_out, int out_size)
{
    const float* x      = (const float*)d_in[0];
    const float* w_qkv  = (const float*)d_in[1];
    const float* w_proj = (const float*)d_in[2];
    float* out = (float*)d_out;

    __half *qkvh, *attnh, *xh, *wqh, *wph;
    cudaGetSymbolAddress((void**)&qkvh,  g_qkvh);
    cudaGetSymbolAddress((void**)&attnh, g_attnh);
    cudaGetSymbolAddress((void**)&xh,    g_xh);
    cudaGetSymbolAddress((void**)&wqh,   g_wqh);
    cudaGetSymbolAddress((void**)&wph,   g_wph);

    cudaFuncSetAttribute(gemm_f16<__half>,
                         cudaFuncAttributeMaxDynamicSharedMemorySize, GEMM_SMEM);
    cudaFuncSetAttribute(gemm_f16<float>,
                         cudaFuncAttributeMaxDynamicSharedMemorySize, GEMM_SMEM);
    cudaFuncSetAttribute(attn_f16,
                         cudaFuncAttributeMaxDynamicSharedMemorySize, ATTN_SMEM);

    // 0) convert inputs/weights to fp16
    int n4x = MROWS * D_MODEL / 4;
    int n4q = QKVDIM * D_MODEL / 4;
    int n4p = D_MODEL * D_MODEL / 4;
    f2h<<<(n4x + 255) / 256, 256>>>((const float4*)x,      (__half2*)xh,  n4x);
    f2h<<<(n4q + 255) / 256, 256>>>((const float4*)w_qkv,  (__half2*)wqh, n4q);
    f2h<<<(n4p + 255) / 256, 256>>>((const float4*)w_proj, (__half2*)wph, n4p);

    // 1) QKV projection (fp16 in, fp16 out)
    dim3 g1(QKVDIM/128, MROWS/128);
    gemm_f16<__half><<<g1, 256, GEMM_SMEM>>>(xh, wqh, qkvh, MROWS, QKVDIM, D_MODEL);

    // 2) causal flash attention (fp16, fp32 softmax)
    dim3 g2(SEQ/128, NHEAD, BATCH);
    attn_f16<<<g2, 256, ATTN_SMEM>>>(qkvh, attnh);

    // 3) output projection (fp16 in, fp32 out)
    dim3 g3(D_MODEL/128, MROWS/128);
    gemm_f16<float><<<g3, 256, GEMM_SMEM>>>(attnh, wph, out, MROWS, D_MODEL, D_MODEL);
}

// round 9
// speedup vs baseline: 1.8530x; 1.0315x over previous
#include <cuda_runtime.h>
#include <cuda_fp16.h>
#include <cstdint>

#define D_MODEL 1024
#define NHEAD   16
#define HDIM    64
#define BATCH   2
#define SEQ     2048
#define MROWS   (BATCH*SEQ)       // 4096
#define QKVDIM  (3*D_MODEL)       // 3072

// Scratch (no cudaMalloc allowed)
__device__ __half g_qkvh [BATCH*SEQ*QKVDIM];   // 25 MB
__device__ __half g_attnh[BATCH*SEQ*D_MODEL];  //  8 MB
__device__ __half g_xh   [MROWS*D_MODEL];      //  8 MB
__device__ __half g_wqh  [QKVDIM*D_MODEL];     //  6 MB
__device__ __half g_wph  [D_MODEL*D_MODEL];    //  2 MB

// ---------------------------------------------------------------------------
// helpers
// ---------------------------------------------------------------------------
static __device__ __forceinline__ uint32_t smem_u32(const void* p) {
    uint32_t a;
    asm("{ .reg .u64 t; cvta.to.shared.u64 t, %1; cvt.u32.u64 %0, t; }"
        : "=r"(a) : "l"(p));
    return a;
}
static __device__ __forceinline__ void mma16(
    float& c0, float& c1, float& c2, float& c3,
    uint32_t a0, uint32_t a1, uint32_t a2, uint32_t a3,
    uint32_t b0, uint32_t b1)
{
    asm volatile(
        "mma.sync.aligned.m16n8k16.row.col.f32.f16.f16.f32 "
        "{%0,%1,%2,%3}, {%4,%5,%6,%7}, {%8,%9}, {%0,%1,%2,%3};"
        : "+f"(c0), "+f"(c1), "+f"(c2), "+f"(c3)
        : "r"(a0), "r"(a1), "r"(a2), "r"(a3), "r"(b0), "r"(b1));
}
static __device__ __forceinline__ void ldmx4(
    uint32_t& r0, uint32_t& r1, uint32_t& r2, uint32_t& r3, uint32_t addr)
{
    asm volatile("ldmatrix.sync.aligned.m8n8.x4.shared.b16 {%0,%1,%2,%3}, [%4];"
                 : "=r"(r0), "=r"(r1), "=r"(r2), "=r"(r3) : "r"(addr));
}
static __device__ __forceinline__ void ldmx4t(
    uint32_t& r0, uint32_t& r1, uint32_t& r2, uint32_t& r3, uint32_t addr)
{
    asm volatile("ldmatrix.sync.aligned.m8n8.x4.trans.shared.b16 {%0,%1,%2,%3}, [%4];"
                 : "=r"(r0), "=r"(r1), "=r"(r2), "=r"(r3) : "r"(addr));
}
static __device__ __forceinline__ void cpa16(uint32_t dst, const void* src) {
    asm volatile("cp.async.ca.shared.global [%0], [%1], 16;"
                 :: "r"(dst), "l"(src) : "memory");
}
static __device__ __forceinline__ void cpa_commit() {
    asm volatile("cp.async.commit_group;" ::: "memory");
}
static __device__ __forceinline__ void cpa_wait1() {
    asm volatile("cp.async.wait_group 1;" ::: "memory");
}
static __device__ __forceinline__ void cpa_wait0() {
    asm volatile("cp.async.wait_group 0;" ::: "memory");
}
static __device__ __forceinline__ void st2h(__half* C, size_t off, float a, float b) {
    *(__half2*)(C + off) = __floats2half2_rn(a, b);
}
static __device__ __forceinline__ void st2h(float* C, size_t off, float a, float b) {
    *(float2*)(C + off) = make_float2(a, b);
}

// ---------------------------------------------------------------------------
// single-launch f32 -> f16 conversion of x, w_qkv, w_proj
// ---------------------------------------------------------------------------
#define N4X (MROWS*D_MODEL/4)
#define N4Q (QKVDIM*D_MODEL/4)
#define N4P (D_MODEL*D_MODEL/4)
__global__ void __launch_bounds__(256) f2h_all(
    const float4* __restrict__ x, const float4* __restrict__ wq,
    const float4* __restrict__ wp,
    __half2* __restrict__ xh, __half2* __restrict__ wqh, __half2* __restrict__ wph)
{
    int i = blockIdx.x * 256 + threadIdx.x;
    const float4* src; __half2* dst; int j;
    if (i < N4X)                { src = x;  dst = xh;  j = i; }
    else if (i < N4X + N4Q)     { src = wq; dst = wqh; j = i - N4X; }
    else if (i < N4X + N4Q + N4P){ src = wp; dst = wph; j = i - N4X - N4Q; }
    else return;
    float4 v = src[j];
    dst[2 * j]     = __floats2half2_rn(v.x, v.y);
    dst[2 * j + 1] = __floats2half2_rn(v.z, v.w);
}

// ===========================================================================
// fp16 mma GEMM (TN): C[m][n] = sum_k A[m*K+k]*B[n*K+k], fp32 accumulate.
// CTA tile 128x128, BK=64 halves (128B rows). 256 thr, 8 warps (2m x 4n),
// warp tile 64x32. Rows swizzled: 16B chunk c at c ^ (row&7).
// 3-stage cp.async. Epilogue scales by qs when bn < q_cols (Q pre-scale).
// ===========================================================================
#define HSTAGE    32768          // A 16KB + B 16KB
#define GEMM_SMEM (3*HSTAGE)     // 98304

template<typename OutT>
__global__ void __launch_bounds__(256, 2) gemm_f16(
    const __half* __restrict__ A, const __half* __restrict__ B,
    OutT* __restrict__ C, int M, int N, int K, int q_cols, float qs)
{
    extern __shared__ char smh[];
    const uint32_t sbase = smem_u32(smh);

    const int tid  = threadIdx.x;
    const int wid  = tid >> 5;
    const int lane = tid & 31;
    const int g    = lane >> 2;
    const int ct   = lane & 3;
    const int wm   = wid & 1;
    const int wn   = wid >> 1;
    const int bm   = blockIdx.y * 128;
    const int bn   = blockIdx.x * 128;
    const float osc = (bn < q_cols) ? qs : 1.0f;

    const int l8 = lane & 7;
    const int h1 = (lane >> 3) & 1;
    const int h2 = lane >> 4;

    uint32_t arow[4], a7[4], brow[2], b7[2];
    #pragma unroll
    for (int mi = 0; mi < 4; mi++) {
        int r = wm * 64 + mi * 16 + l8 + h1 * 8;
        arow[mi] = (uint32_t)(r * 128);
        a7[mi]   = (uint32_t)(r & 7);
    }
    #pragma unroll
    for (int p = 0; p < 2; p++) {
        int r = wn * 32 + p * 16 + l8 + h2 * 8;
        brow[p] = 16384u + (uint32_t)(r * 128);
        b7[p]   = (uint32_t)(r & 7);
    }

    const int crow = tid >> 1;
    const int cc0  = (tid & 1) * 4;
    const __half* Ag = A + (size_t)(bm + crow) * K;
    const __half* Bg = B + (size_t)(bn + crow) * K;
    uint32_t dwa[4], dwb[4];
    #pragma unroll
    for (int i = 0; i < 4; i++) {
        uint32_t sw = (uint32_t)(((cc0 + i) ^ (crow & 7)) * 16);
        dwa[i] = (uint32_t)(crow * 128) + sw;
        dwb[i] = 16384u + (uint32_t)(crow * 128) + sw;
    }

    const int nkt = K / 64;

    float acc[4][4][4];
    #pragma unroll
    for (int i = 0; i < 4; i++)
        #pragma unroll
        for (int j = 0; j < 4; j++)
            #pragma unroll
            for (int e = 0; e < 4; e++) acc[i][j][e] = 0.f;

    #pragma unroll
    for (int s = 0; s < 2; s++) {
        uint32_t st = sbase + (uint32_t)s * HSTAGE;
        #pragma unroll
        for (int i = 0; i < 4; i++) {
            cpa16(st + dwa[i], Ag + s * 64 + (cc0 + i) * 8);
            cpa16(st + dwb[i], Bg + s * 64 + (cc0 + i) * 8);
        }
        cpa_commit();
    }

    int sc = 0;
    for (int kt = 0; kt < nkt; kt++) {
        cpa_wait1();
        __syncthreads();

        if (kt + 2 < nkt) {
            int sn = sc + 2; if (sn >= 3) sn -= 3;
            uint32_t st = sbase + (uint32_t)sn * HSTAGE;
            #pragma unroll
            for (int i = 0; i < 4; i++) {
                cpa16(st + dwa[i], Ag + (kt + 2) * 64 + (cc0 + i) * 8);
                cpa16(st + dwb[i], Bg + (kt + 2) * 64 + (cc0 + i) * 8);
            }
        }
        cpa_commit();

        const uint32_t cbase = sbase + (uint32_t)sc * HSTAGE;
        #pragma unroll
        for (int ks = 0; ks < 4; ks++) {
            uint32_t a[4][4], bb[2][4];
            #pragma unroll
            for (int mi = 0; mi < 4; mi++)
                ldmx4(a[mi][0], a[mi][1], a[mi][2], a[mi][3],
                      cbase + arow[mi] + ((((uint32_t)(ks * 2 + h2)) ^ a7[mi]) << 4));
            #pragma unroll
            for (int p = 0; p < 2; p++)
                ldmx4(bb[p][0], bb[p][1], bb[p][2], bb[p][3],
                      cbase + brow[p] + ((((uint32_t)(ks * 2 + h1)) ^ b7[p]) << 4));
            #pragma unroll
            for (int mi = 0; mi < 4; mi++)
                #pragma unroll
                for (int nt = 0; nt < 4; nt++)
                    mma16(acc[mi][nt][0], acc[mi][nt][1], acc[mi][nt][2], acc[mi][nt][3],
                          a[mi][0], a[mi][1], a[mi][2], a[mi][3],
                          bb[nt >> 1][(nt & 1) * 2], bb[nt >> 1][(nt & 1) * 2 + 1]);
        }
        sc++; if (sc >= 3) sc -= 3;
    }

    #pragma unroll
    for (int mi = 0; mi < 4; mi++) {
        int r0 = bm + wm * 64 + mi * 16 + g;
        #pragma unroll
        for (int nt = 0; nt < 4; nt++) {
            int c0 = bn + wn * 32 + nt * 8 + 2 * ct;
            st2h(C, (size_t)r0 * N + c0,
                 acc[mi][nt][0] * osc, acc[mi][nt][1] * osc);
            st2h(C, (size_t)(r0 + 8) * N + c0,
                 acc[mi][nt][2] * osc, acc[mi][nt][3] * osc);
        }
    }
}

// ===========================================================================
// Flash attention, fp16 mma, 2-stage cp.async pipelined K/V tiles.
// Q tile 128 (pre-scaled by 0.125 in QKV GEMM), K/V tile 64, d=64.
// 8 warps, warp w owns rows [w*16, w*16+16). Rows 128B, chunk-swizzle
// c ^ (row&7). V via ldmatrix.trans.
// smem: Q 16K | K 2x8K | V 2x8K | P 16K = 64K
// ===========================================================================
#define AQ_OFF 0
#define AK_OFF 16384
#define AV_OFF 32768
#define AP_OFF 49152
#define ATTN_SMEM 65536

__global__ void __launch_bounds__(256) attn_f16(
    const __half* __restrict__ qkv, __half* __restrict__ attn_out)
{
    extern __shared__ char smh[];
    const uint32_t sb = smem_u32(smh);

    const int qt  = (int)gridDim.x - 1 - (int)blockIdx.x;  // heavy blocks first
    const int h   = blockIdx.y;
    const int b   = blockIdx.z;
    const int tid = threadIdx.x;
    const int wid = tid >> 5;
    const int lane = tid & 31;
    const int g   = lane >> 2;
    const int ct  = lane & 3;
    const int q0  = qt * 128;
    const int rl  = wid * 16 + g;

    const int l8 = lane & 7;
    const int h1 = (lane >> 3) & 1;
    const int h2 = lane >> 4;

    const int arow = wid * 16 + l8 + h1 * 8;
    const uint32_t qbase = sb + AQ_OFF + (uint32_t)(arow * 128);
    const uint32_t pbase = sb + AP_OFF + (uint32_t)(arow * 128);
    const uint32_t a7 = (uint32_t)(arow & 7);
    uint32_t krow[4], k7[4];
    #pragma unroll
    for (int p = 0; p < 4; p++) {
        int r = p * 16 + l8 + h2 * 8;
        krow[p] = (uint32_t)(r * 128);
        k7[p]   = (uint32_t)(r & 7);
    }
    const int vr0 = l8 + h1 * 8;

    const size_t rs = QKVDIM;
    const __half* Qg = qkv + (size_t)b * SEQ * rs + h * HDIM;
    const __half* Kg = Qg + D_MODEL;
    const __half* Vg = Qg + 2 * D_MODEL;

    // K/V cp.async mapping: thread -> 2 chunks each (64 rows x 8 chunks / 256 thr)
    const int krr0 = tid >> 3;          // rows tid>>3 and tid>>3 + 32
    const int kc   = tid & 7;
    const uint32_t ksw0 = (uint32_t)(krr0 * 128 + ((kc ^ (krr0 & 7)) * 16));
    const int krr1 = krr0 + 32;
    const uint32_t ksw1 = (uint32_t)(krr1 * 128 + ((kc ^ (krr1 & 7)) * 16));

    // load Q tile (LDG/STS; once)
    #pragma unroll
    for (int it = 0; it < 4; it++) {
        int idx = tid + it * 256;
        int rr  = idx >> 3;
        int c   = idx & 7;
        uint4 v = *(const uint4*)(Qg + (size_t)(q0 + rr) * rs + c * 8);
        *(uint4*)(smh + AQ_OFF + rr * 128 + ((c ^ (rr & 7)) * 16)) = v;
    }

    const int nkt = 2 * qt + 2;

    // prologue: issue kt=0 K/V into stage 0
    {
        const __half* Ksrc = Kg;
        const __half* Vsrc = Vg;
        cpa16(sb + AK_OFF + ksw0, Ksrc + (size_t)krr0 * rs + kc * 8);
        cpa16(sb + AK_OFF + ksw1, Ksrc + (size_t)krr1 * rs + kc * 8);
        cpa16(sb + AV_OFF + ksw0, Vsrc + (size_t)krr0 * rs + kc * 8);
        cpa16(sb + AV_OFF + ksw1, Vsrc + (size_t)krr1 * rs + kc * 8);
        cpa_commit();
    }

    float m_lo = -1e30f, m_hi = -1e30f, l_lo = 0.f, l_hi = 0.f;
    float o[8][4];
    #pragma unroll
    for (int nt = 0; nt < 8; nt++)
        #pragma unroll
        for (int e = 0; e < 4; e++) o[nt][e] = 0.f;

    for (int kt = 0; kt < nkt; kt++) {
        cpa_wait0();          // stage kt&1 ready
        __syncthreads();      // all warps done with stage (kt+1)&1's old data

        if (kt + 1 < nkt) {   // issue kt+1 into the other stage, overlapped
            const int k1 = (kt + 1) * 64;
            const uint32_t so = (uint32_t)((kt + 1) & 1) * 8192u;
            cpa16(sb + AK_OFF + so + ksw0, Kg + (size_t)(k1 + krr0) * rs + kc * 8);
            cpa16(sb + AK_OFF + so + ksw1, Kg + (size_t)(k1 + krr1) * rs + kc * 8);
            cpa16(sb + AV_OFF + so + ksw0, Vg + (size_t)(k1 + krr0) * rs + kc * 8);
            cpa16(sb + AV_OFF + so + ksw1, Vg + (size_t)(k1 + krr1) * rs + kc * 8);
            cpa_commit();
        }

        const int k0 = kt * 64;
        if (k0 > q0 + wid * 16 + 15) continue;   // fully above diagonal

        const uint32_t kb = sb + AK_OFF + (uint32_t)(kt & 1) * 8192u;
        const uint32_t vb = sb + AV_OFF + (uint32_t)(kt & 1) * 8192u;

        // ---- S = Q K^T (Q pre-scaled by 0.125) ----
        float s[8][4];
        #pragma unroll
        for (int nt = 0; nt < 8; nt++)
            #pragma unroll
            for (int e = 0; e < 4; e++) s[nt][e] = 0.f;

        #pragma unroll
        for (int ks = 0; ks < 4; ks++) {
            uint32_t a0, a1, a2, a3;
            ldmx4(a0, a1, a2, a3, qbase + ((((uint32_t)(ks * 2 + h2)) ^ a7) << 4));
            #pragma unroll
            for (int p = 0; p < 4; p++) {
                uint32_t b0, b1, b2, b3;
                ldmx4(b0, b1, b2, b3, kb + krow[p] + ((((uint32_t)(ks * 2 + h1)) ^ k7[p]) << 4));
                mma16(s[2*p][0], s[2*p][1], s[2*p][2], s[2*p][3],
                      a0, a1, a2, a3, b0, b1);
                mma16(s[2*p+1][0], s[2*p+1][1], s[2*p+1][2], s[2*p+1][3],
                      a0, a1, a2, a3, b2, b3);
            }
        }

        // ---- causal mask ----
        const int rglo = q0 + rl;
        const int rghi = rglo + 8;
        if (k0 + 63 > rglo) {
            #pragma unroll
            for (int nt = 0; nt < 8; nt++) {
                int key = k0 + nt * 8 + 2 * ct;
                if (key     > rglo) s[nt][0] = -1e30f;
                if (key + 1 > rglo) s[nt][1] = -1e30f;
                if (key     > rghi) s[nt][2] = -1e30f;
                if (key + 1 > rghi) s[nt][3] = -1e30f;
            }
        }

        // ---- online softmax (quad reduce) ----
        float tlo = -1e30f, thi = -1e30f;
        #pragma unroll
        for (int nt = 0; nt < 8; nt++) {
            tlo = fmaxf(tlo, fmaxf(s[nt][0], s[nt][1]));
            thi = fmaxf(thi, fmaxf(s[nt][2], s[nt][3]));
        }
        tlo = fmaxf(tlo, __shfl_xor_sync(0xffffffffu, tlo, 1));
        tlo = fmaxf(tlo, __shfl_xor_sync(0xffffffffu, tlo, 2));
        thi = fmaxf(thi, __shfl_xor_sync(0xffffffffu, thi, 1));
        thi = fmaxf(thi, __shfl_xor_sync(0xffffffffu, thi, 2));

        float mn_lo = fmaxf(m_lo, tlo);
        float mn_hi = fmaxf(m_hi, thi);
        float al_lo = __expf(m_lo - mn_lo);
        float al_hi = __expf(m_hi - mn_hi);
        m_lo = mn_lo; m_hi = mn_hi;

        float ps_lo = 0.f, ps_hi = 0.f;
        #pragma unroll
        for (int nt = 0; nt < 8; nt++) {
            float p0 = __expf(s[nt][0] - mn_lo);
            float p1 = __expf(s[nt][1] - mn_lo);
            float p2 = __expf(s[nt][2] - mn_hi);
            float p3 = __expf(s[nt][3] - mn_hi);
            ps_lo += p0 + p1;
            ps_hi += p2 + p3;
            uint32_t swl = (uint32_t)(rl * 128 + (((nt) ^ (rl & 7)) * 16) + 4 * ct);
            uint32_t swh = (uint32_t)((rl + 8) * 128 + (((nt) ^ ((rl + 8) & 7)) * 16) + 4 * ct);
            *(__half2*)(smh + AP_OFF + swl) = __floats2half2_rn(p0, p1);
            *(__half2*)(smh + AP_OFF + swh) = __floats2half2_rn(p2, p3);
        }
        ps_lo += __shfl_xor_sync(0xffffffffu, ps_lo, 1);
        ps_lo += __shfl_xor_sync(0xffffffffu, ps_lo, 2);
        ps_hi += __shfl_xor_sync(0xffffffffu, ps_hi, 1);
        ps_hi += __shfl_xor_sync(0xffffffffu, ps_hi, 2);
        l_lo = l_lo * al_lo + ps_lo;
        l_hi = l_hi * al_hi + ps_hi;

        #pragma unroll
        for (int nt = 0; nt < 8; nt++) {
            o[nt][0] *= al_lo; o[nt][1] *= al_lo;
            o[nt][2] *= al_hi; o[nt][3] *= al_hi;
        }
        __syncwarp();

        // ---- O += P V (V via ldmatrix.trans) ----
        #pragma unroll
        for (int ks = 0; ks < 4; ks++) {
            uint32_t a0, a1, a2, a3;
            ldmx4(a0, a1, a2, a3, pbase + ((((uint32_t)(ks * 2 + h2)) ^ a7) << 4));
            int vrow = ks * 16 + vr0;
            uint32_t vbase = vb + (uint32_t)(vrow * 128);
            uint32_t v7 = (uint32_t)(vrow & 7);
            #pragma unroll
            for (int pn = 0; pn < 4; pn++) {
                uint32_t b0, b1, b2, b3;
                ldmx4t(b0, b1, b2, b3, vbase + ((((uint32_t)(pn * 2 + h2)) ^ v7) << 4));
                mma16(o[2*pn][0], o[2*pn][1], o[2*pn][2], o[2*pn][3],
                      a0, a1, a2, a3, b0, b1);
                mma16(o[2*pn+1][0], o[2*pn+1][1], o[2*pn+1][2], o[2*pn+1][3],
                      a0, a1, a2, a3, b2, b3);
            }
        }
    }

    float inv_lo = 1.0f / l_lo;
    float inv_hi = 1.0f / l_hi;
    __half* Og = attn_out + (size_t)(b * SEQ + q0) * D_MODEL + h * HDIM;
    #pragma unroll
    for (int nt = 0; nt < 8; nt++) {
        int col = nt * 8 + 2 * ct;
        *(__half2*)&Og[(size_t)rl * D_MODEL + col] =
            __floats2half2_rn(o[nt][0] * inv_lo, o[nt][1] * inv_lo);
        *(__half2*)&Og[(size_t)(rl + 8) * D_MODEL + col] =
            __floats2half2_rn(o[nt][2] * inv_hi, o[nt][3] * inv_hi);
    }
}

// ===========================================================================
extern "C" void kernel_launch(void* const* d_in, const int* in_sizes, int n_in,
                              void* d_out, int out_size)
{
    const float* x      = (const float*)d_in[0];
    const float* w_qkv  = (const float*)d_in[1];
    const float* w_proj = (const float*)d_in[2];
    float* out = (float*)d_out;

    __half *qkvh, *attnh, *xh, *wqh, *wph;
    cudaGetSymbolAddress((void**)&qkvh,  g_qkvh);
    cudaGetSymbolAddress((void**)&attnh, g_attnh);
    cudaGetSymbolAddress((void**)&xh,    g_xh);
    cudaGetSymbolAddress((void**)&wqh,   g_wqh);
    cudaGetSymbolAddress((void**)&wph,   g_wph);

    cudaFuncSetAttribute(gemm_f16<__half>,
                         cudaFuncAttributeMaxDynamicSharedMemorySize, GEMM_SMEM);
    cudaFuncSetAttribute(gemm_f16<float>,
                         cudaFuncAttributeMaxDynamicSharedMemorySize, GEMM_SMEM);
    cudaFuncSetAttribute(attn_f16,
                         cudaFuncAttributeMaxDynamicSharedMemorySize, ATTN_SMEM);

    // 0) convert inputs/weights to fp16 (one launch)
    int n4 = N4X + N4Q + N4P;
    f2h_all<<<(n4 + 255) / 256, 256>>>(
        (const float4*)x, (const float4*)w_qkv, (const float4*)w_proj,
        (__half2*)xh, (__half2*)wqh, (__half2*)wph);

    // 1) QKV projection; Q columns (n < 1024) pre-scaled by 1/8
    dim3 g1(QKVDIM/128, MROWS/128);
    gemm_f16<__half><<<g1, 256, GEMM_SMEM>>>(xh, wqh, qkvh,
                                             MROWS, QKVDIM, D_MODEL,
                                             D_MODEL, 0.125f);

    // 2) causal flash attention (fp16, fp32 softmax), pipelined K/V
    dim3 g2(SEQ/128, NHEAD, BATCH);
    attn_f16<<<g2, 256, ATTN_SMEM>>>(qkvh, attnh);

    // 3) output projection (fp16 in, fp32 out)
    dim3 g3(D_MODEL/128, MROWS/128);
    gemm_f16<float><<<g3, 256, GEMM_SMEM>>>(attnh, wph, out,
                                            MROWS, D_MODEL, D_MODEL,
                                            0, 1.0f);
}

// round 10
// speedup vs baseline: 1.9443x; 1.0493x over previous
#include <cuda_runtime.h>
#include <cuda_fp16.h>
#include <cstdint>

#define D_MODEL 1024
#define NHEAD   16
#define HDIM    64
#define BATCH   2
#define SEQ     2048
#define MROWS   (BATCH*SEQ)       // 4096
#define QKVDIM  (3*D_MODEL)       // 3072

// Scratch (no cudaMalloc allowed)
__device__ __half g_qkvh [BATCH*SEQ*QKVDIM];   // 25 MB
__device__ __half g_attnh[BATCH*SEQ*D_MODEL];  //  8 MB
__device__ __half g_xh   [MROWS*D_MODEL];      //  8 MB
__device__ __half g_wqh  [QKVDIM*D_MODEL];     //  6 MB
__device__ __half g_wph  [D_MODEL*D_MODEL];    //  2 MB

// ---------------------------------------------------------------------------
// helpers
// ---------------------------------------------------------------------------
static __device__ __forceinline__ uint32_t smem_u32(const void* p) {
    uint32_t a;
    asm("{ .reg .u64 t; cvta.to.shared.u64 t, %1; cvt.u32.u64 %0, t; }"
        : "=r"(a) : "l"(p));
    return a;
}
static __device__ __forceinline__ void mma16(
    float& c0, float& c1, float& c2, float& c3,
    uint32_t a0, uint32_t a1, uint32_t a2, uint32_t a3,
    uint32_t b0, uint32_t b1)
{
    asm volatile(
        "mma.sync.aligned.m16n8k16.row.col.f32.f16.f16.f32 "
        "{%0,%1,%2,%3}, {%4,%5,%6,%7}, {%8,%9}, {%0,%1,%2,%3};"
        : "+f"(c0), "+f"(c1), "+f"(c2), "+f"(c3)
        : "r"(a0), "r"(a1), "r"(a2), "r"(a3), "r"(b0), "r"(b1));
}
static __device__ __forceinline__ void ldmx4(
    uint32_t& r0, uint32_t& r1, uint32_t& r2, uint32_t& r3, uint32_t addr)
{
    asm volatile("ldmatrix.sync.aligned.m8n8.x4.shared.b16 {%0,%1,%2,%3}, [%4];"
                 : "=r"(r0), "=r"(r1), "=r"(r2), "=r"(r3) : "r"(addr));
}
static __device__ __forceinline__ void ldmx4t(
    uint32_t& r0, uint32_t& r1, uint32_t& r2, uint32_t& r3, uint32_t addr)
{
    asm volatile("ldmatrix.sync.aligned.m8n8.x4.trans.shared.b16 {%0,%1,%2,%3}, [%4];"
                 : "=r"(r0), "=r"(r1), "=r"(r2), "=r"(r3) : "r"(addr));
}
static __device__ __forceinline__ void cpa16(uint32_t dst, const void* src) {
    asm volatile("cp.async.ca.shared.global [%0], [%1], 16;"
                 :: "r"(dst), "l"(src) : "memory");
}
static __device__ __forceinline__ void cpa_commit() {
    asm volatile("cp.async.commit_group;" ::: "memory");
}
static __device__ __forceinline__ void cpa_wait1() {
    asm volatile("cp.async.wait_group 1;" ::: "memory");
}
static __device__ __forceinline__ void cpa_wait0() {
    asm volatile("cp.async.wait_group 0;" ::: "memory");
}
static __device__ __forceinline__ void st2h(__half* C, size_t off, float a, float b) {
    *(__half2*)(C + off) = __floats2half2_rn(a, b);
}
static __device__ __forceinline__ void st2h(float* C, size_t off, float a, float b) {
    *(float2*)(C + off) = make_float2(a, b);
}
static __device__ __forceinline__ uint32_t packh2(float a, float b) {
    __half2 h = __floats2half2_rn(a, b);
    return *(uint32_t*)&h;
}

// ---------------------------------------------------------------------------
// single-launch f32 -> f16 conversion of x, w_qkv, w_proj
// ---------------------------------------------------------------------------
#define N4X (MROWS*D_MODEL/4)
#define N4Q (QKVDIM*D_MODEL/4)
#define N4P (D_MODEL*D_MODEL/4)
__global__ void __launch_bounds__(256) f2h_all(
    const float4* __restrict__ x, const float4* __restrict__ wq,
    const float4* __restrict__ wp,
    __half2* __restrict__ xh, __half2* __restrict__ wqh, __half2* __restrict__ wph)
{
    int i = blockIdx.x * 256 + threadIdx.x;
    const float4* src; __half2* dst; int j;
    if (i < N4X)                { src = x;  dst = xh;  j = i; }
    else if (i < N4X + N4Q)     { src = wq; dst = wqh; j = i - N4X; }
    else if (i < N4X + N4Q + N4P){ src = wp; dst = wph; j = i - N4X - N4Q; }
    else return;
    float4 v = src[j];
    dst[2 * j]     = __floats2half2_rn(v.x, v.y);
    dst[2 * j + 1] = __floats2half2_rn(v.z, v.w);
}

// ===========================================================================
// fp16 mma GEMM (TN): unchanged from round 9.
// ===========================================================================
#define HSTAGE    32768
#define GEMM_SMEM (3*HSTAGE)

template<typename OutT>
__global__ void __launch_bounds__(256, 2) gemm_f16(
    const __half* __restrict__ A, const __half* __restrict__ B,
    OutT* __restrict__ C, int M, int N, int K, int q_cols, float qs)
{
    extern __shared__ char smh[];
    const uint32_t sbase = smem_u32(smh);

    const int tid  = threadIdx.x;
    const int wid  = tid >> 5;
    const int lane = tid & 31;
    const int g    = lane >> 2;
    const int ct   = lane & 3;
    const int wm   = wid & 1;
    const int wn   = wid >> 1;
    const int bm   = blockIdx.y * 128;
    const int bn   = blockIdx.x * 128;
    const float osc = (bn < q_cols) ? qs : 1.0f;

    const int l8 = lane & 7;
    const int h1 = (lane >> 3) & 1;
    const int h2 = lane >> 4;

    uint32_t arow[4], a7[4], brow[2], b7[2];
    #pragma unroll
    for (int mi = 0; mi < 4; mi++) {
        int r = wm * 64 + mi * 16 + l8 + h1 * 8;
        arow[mi] = (uint32_t)(r * 128);
        a7[mi]   = (uint32_t)(r & 7);
    }
    #pragma unroll
    for (int p = 0; p < 2; p++) {
        int r = wn * 32 + p * 16 + l8 + h2 * 8;
        brow[p] = 16384u + (uint32_t)(r * 128);
        b7[p]   = (uint32_t)(r & 7);
    }

    const int crow = tid >> 1;
    const int cc0  = (tid & 1) * 4;
    const __half* Ag = A + (size_t)(bm + crow) * K;
    const __half* Bg = B + (size_t)(bn + crow) * K;
    uint32_t dwa[4], dwb[4];
    #pragma unroll
    for (int i = 0; i < 4; i++) {
        uint32_t sw = (uint32_t)(((cc0 + i) ^ (crow & 7)) * 16);
        dwa[i] = (uint32_t)(crow * 128) + sw;
        dwb[i] = 16384u + (uint32_t)(crow * 128) + sw;
    }

    const int nkt = K / 64;

    float acc[4][4][4];
    #pragma unroll
    for (int i = 0; i < 4; i++)
        #pragma unroll
        for (int j = 0; j < 4; j++)
            #pragma unroll
            for (int e = 0; e < 4; e++) acc[i][j][e] = 0.f;

    #pragma unroll
    for (int s = 0; s < 2; s++) {
        uint32_t st = sbase + (uint32_t)s * HSTAGE;
        #pragma unroll
        for (int i = 0; i < 4; i++) {
            cpa16(st + dwa[i], Ag + s * 64 + (cc0 + i) * 8);
            cpa16(st + dwb[i], Bg + s * 64 + (cc0 + i) * 8);
        }
        cpa_commit();
    }

    int sc = 0;
    for (int kt = 0; kt < nkt; kt++) {
        cpa_wait1();
        __syncthreads();

        if (kt + 2 < nkt) {
            int sn = sc + 2; if (sn >= 3) sn -= 3;
            uint32_t st = sbase + (uint32_t)sn * HSTAGE;
            #pragma unroll
            for (int i = 0; i < 4; i++) {
                cpa16(st + dwa[i], Ag + (kt + 2) * 64 + (cc0 + i) * 8);
                cpa16(st + dwb[i], Bg + (kt + 2) * 64 + (cc0 + i) * 8);
            }
        }
        cpa_commit();

        const uint32_t cbase = sbase + (uint32_t)sc * HSTAGE;
        #pragma unroll
        for (int ks = 0; ks < 4; ks++) {
            uint32_t a[4][4], bb[2][4];
            #pragma unroll
            for (int mi = 0; mi < 4; mi++)
                ldmx4(a[mi][0], a[mi][1], a[mi][2], a[mi][3],
                      cbase + arow[mi] + ((((uint32_t)(ks * 2 + h2)) ^ a7[mi]) << 4));
            #pragma unroll
            for (int p = 0; p < 2; p++)
                ldmx4(bb[p][0], bb[p][1], bb[p][2], bb[p][3],
                      cbase + brow[p] + ((((uint32_t)(ks * 2 + h1)) ^ b7[p]) << 4));
            #pragma unroll
            for (int mi = 0; mi < 4; mi++)
                #pragma unroll
                for (int nt = 0; nt < 4; nt++)
                    mma16(acc[mi][nt][0], acc[mi][nt][1], acc[mi][nt][2], acc[mi][nt][3],
                          a[mi][0], a[mi][1], a[mi][2], a[mi][3],
                          bb[nt >> 1][(nt & 1) * 2], bb[nt >> 1][(nt & 1) * 2 + 1]);
        }
        sc++; if (sc >= 3) sc -= 3;
    }

    #pragma unroll
    for (int mi = 0; mi < 4; mi++) {
        int r0 = bm + wm * 64 + mi * 16 + g;
        #pragma unroll
        for (int nt = 0; nt < 4; nt++) {
            int c0 = bn + wn * 32 + nt * 8 + 2 * ct;
            st2h(C, (size_t)r0 * N + c0,
                 acc[mi][nt][0] * osc, acc[mi][nt][1] * osc);
            st2h(C, (size_t)(r0 + 8) * N + c0,
                 acc[mi][nt][2] * osc, acc[mi][nt][3] * osc);
        }
    }
}

// ===========================================================================
// Flash attention, fp16 mma, 2-stage cp.async pipelined K/V, P IN REGISTERS
// (FA2: S-fragment of QK^T == A-fragment for PV; no P smem, no extra sync).
// Q tile 128 (pre-scaled by 0.125), K/V tile 64, d=64.
// smem: Q 16K | K 2x8K | V 2x8K = 48K -> 2 CTAs/SM.
// ===========================================================================
#define AQ_OFF 0
#define AK_OFF 16384
#define AV_OFF 32768
#define ATTN_SMEM 49152

__global__ void __launch_bounds__(256, 2) attn_f16(
    const __half* __restrict__ qkv, __half* __restrict__ attn_out)
{
    extern __shared__ char smh[];
    const uint32_t sb = smem_u32(smh);

    const int qt  = (int)gridDim.x - 1 - (int)blockIdx.x;  // heavy blocks first
    const int h   = blockIdx.y;
    const int b   = blockIdx.z;
    const int tid = threadIdx.x;
    const int wid = tid >> 5;
    const int lane = tid & 31;
    const int g   = lane >> 2;
    const int ct  = lane & 3;
    const int q0  = qt * 128;
    const int rl  = wid * 16 + g;

    const int l8 = lane & 7;
    const int h1 = (lane >> 3) & 1;
    const int h2 = lane >> 4;

    const int arow = wid * 16 + l8 + h1 * 8;
    const uint32_t qbase = sb + AQ_OFF + (uint32_t)(arow * 128);
    const uint32_t a7 = (uint32_t)(arow & 7);
    uint32_t krow[4], k7[4];
    #pragma unroll
    for (int p = 0; p < 4; p++) {
        int r = p * 16 + l8 + h2 * 8;
        krow[p] = (uint32_t)(r * 128);
        k7[p]   = (uint32_t)(r & 7);
    }
    const int vr0 = l8 + h1 * 8;

    const size_t rs = QKVDIM;
    const __half* Qg = qkv + (size_t)b * SEQ * rs + h * HDIM;
    const __half* Kg = Qg + D_MODEL;
    const __half* Vg = Qg + 2 * D_MODEL;

    // K/V cp.async mapping: thread -> 2 chunks each (64 rows x 8 chunks)
    const int krr0 = tid >> 3;
    const int kc   = tid & 7;
    const uint32_t ksw0 = (uint32_t)(krr0 * 128 + ((kc ^ (krr0 & 7)) * 16));
    const int krr1 = krr0 + 32;
    const uint32_t ksw1 = (uint32_t)(krr1 * 128 + ((kc ^ (krr1 & 7)) * 16));

    // load Q tile (once)
    #pragma unroll
    for (int it = 0; it < 4; it++) {
        int idx = tid + it * 256;
        int rr  = idx >> 3;
        int c   = idx & 7;
        uint4 v = *(const uint4*)(Qg + (size_t)(q0 + rr) * rs + c * 8);
        *(uint4*)(smh + AQ_OFF + rr * 128 + ((c ^ (rr & 7)) * 16)) = v;
    }

    const int nkt = 2 * qt + 2;

    // prologue: kt=0 K/V into stage 0
    cpa16(sb + AK_OFF + ksw0, Kg + (size_t)krr0 * rs + kc * 8);
    cpa16(sb + AK_OFF + ksw1, Kg + (size_t)krr1 * rs + kc * 8);
    cpa16(sb + AV_OFF + ksw0, Vg + (size_t)krr0 * rs + kc * 8);
    cpa16(sb + AV_OFF + ksw1, Vg + (size_t)krr1 * rs + kc * 8);
    cpa_commit();

    float m_lo = -1e30f, m_hi = -1e30f, l_lo = 0.f, l_hi = 0.f;
    float o[8][4];
    #pragma unroll
    for (int nt = 0; nt < 8; nt++)
        #pragma unroll
        for (int e = 0; e < 4; e++) o[nt][e] = 0.f;

    for (int kt = 0; kt < nkt; kt++) {
        cpa_wait0();
        __syncthreads();

        if (kt + 1 < nkt) {
            const int k1 = (kt + 1) * 64;
            const uint32_t so = (uint32_t)((kt + 1) & 1) * 8192u;
            cpa16(sb + AK_OFF + so + ksw0, Kg + (size_t)(k1 + krr0) * rs + kc * 8);
            cpa16(sb + AK_OFF + so + ksw1, Kg + (size_t)(k1 + krr1) * rs + kc * 8);
            cpa16(sb + AV_OFF + so + ksw0, Vg + (size_t)(k1 + krr0) * rs + kc * 8);
            cpa16(sb + AV_OFF + so + ksw1, Vg + (size_t)(k1 + krr1) * rs + kc * 8);
            cpa_commit();
        }

        const int k0 = kt * 64;
        if (k0 > q0 + wid * 16 + 15) continue;

        const uint32_t kb = sb + AK_OFF + (uint32_t)(kt & 1) * 8192u;
        const uint32_t vb = sb + AV_OFF + (uint32_t)(kt & 1) * 8192u;

        // ---- S = Q K^T ----
        float s[8][4];
        #pragma unroll
        for (int nt = 0; nt < 8; nt++)
            #pragma unroll
            for (int e = 0; e < 4; e++) s[nt][e] = 0.f;

        #pragma unroll
        for (int ks = 0; ks < 4; ks++) {
            uint32_t a0, a1, a2, a3;
            ldmx4(a0, a1, a2, a3, qbase + ((((uint32_t)(ks * 2 + h2)) ^ a7) << 4));
            #pragma unroll
            for (int p = 0; p < 4; p++) {
                uint32_t b0, b1, b2, b3;
                ldmx4(b0, b1, b2, b3, kb + krow[p] + ((((uint32_t)(ks * 2 + h1)) ^ k7[p]) << 4));
                mma16(s[2*p][0], s[2*p][1], s[2*p][2], s[2*p][3],
                      a0, a1, a2, a3, b0, b1);
                mma16(s[2*p+1][0], s[2*p+1][1], s[2*p+1][2], s[2*p+1][3],
                      a0, a1, a2, a3, b2, b3);
            }
        }

        // ---- causal mask ----
        const int rglo = q0 + rl;
        const int rghi = rglo + 8;
        if (k0 + 63 > rglo) {
            #pragma unroll
            for (int nt = 0; nt < 8; nt++) {
                int key = k0 + nt * 8 + 2 * ct;
                if (key     > rglo) s[nt][0] = -1e30f;
                if (key + 1 > rglo) s[nt][1] = -1e30f;
                if (key     > rghi) s[nt][2] = -1e30f;
                if (key + 1 > rghi) s[nt][3] = -1e30f;
            }
        }

        // ---- online softmax (quad reduce) ----
        float tlo = -1e30f, thi = -1e30f;
        #pragma unroll
        for (int nt = 0; nt < 8; nt++) {
            tlo = fmaxf(tlo, fmaxf(s[nt][0], s[nt][1]));
            thi = fmaxf(thi, fmaxf(s[nt][2], s[nt][3]));
        }
        tlo = fmaxf(tlo, __shfl_xor_sync(0xffffffffu, tlo, 1));
        tlo = fmaxf(tlo, __shfl_xor_sync(0xffffffffu, tlo, 2));
        thi = fmaxf(thi, __shfl_xor_sync(0xffffffffu, thi, 1));
        thi = fmaxf(thi, __shfl_xor_sync(0xffffffffu, thi, 2));

        float mn_lo = fmaxf(m_lo, tlo);
        float mn_hi = fmaxf(m_hi, thi);
        float al_lo = __expf(m_lo - mn_lo);
        float al_hi = __expf(m_hi - mn_hi);
        m_lo = mn_lo; m_hi = mn_hi;

        // ---- exp + pack P directly into A-fragments (no smem) ----
        uint32_t plo[8], phi[8];
        float ps_lo = 0.f, ps_hi = 0.f;
        #pragma unroll
        for (int nt = 0; nt < 8; nt++) {
            float p0 = __expf(s[nt][0] - mn_lo);
            float p1 = __expf(s[nt][1] - mn_lo);
            float p2 = __expf(s[nt][2] - mn_hi);
            float p3 = __expf(s[nt][3] - mn_hi);
            ps_lo += p0 + p1;
            ps_hi += p2 + p3;
            plo[nt] = packh2(p0, p1);
            phi[nt] = packh2(p2, p3);
        }
        ps_lo += __shfl_xor_sync(0xffffffffu, ps_lo, 1);
        ps_lo += __shfl_xor_sync(0xffffffffu, ps_lo, 2);
        ps_hi += __shfl_xor_sync(0xffffffffu, ps_hi, 1);
        ps_hi += __shfl_xor_sync(0xffffffffu, ps_hi, 2);
        l_lo = l_lo * al_lo + ps_lo;
        l_hi = l_hi * al_hi + ps_hi;

        #pragma unroll
        for (int nt = 0; nt < 8; nt++) {
            o[nt][0] *= al_lo; o[nt][1] *= al_lo;
            o[nt][2] *= al_hi; o[nt][3] *= al_hi;
        }

        // ---- O += P V (P from registers; V via ldmatrix.trans) ----
        #pragma unroll
        for (int ks = 0; ks < 4; ks++) {
            uint32_t a0 = plo[2*ks], a1 = phi[2*ks];
            uint32_t a2 = plo[2*ks+1], a3 = phi[2*ks+1];
            int vrow = ks * 16 + vr0;
            uint32_t vbase = vb + (uint32_t)(vrow * 128);
            uint32_t v7 = (uint32_t)(vrow & 7);
            #pragma unroll
            for (int pn = 0; pn < 4; pn++) {
                uint32_t b0, b1, b2, b3;
                ldmx4t(b0, b1, b2, b3, vbase + ((((uint32_t)(pn * 2 + h2)) ^ v7) << 4));
                mma16(o[2*pn][0], o[2*pn][1], o[2*pn][2], o[2*pn][3],
                      a0, a1, a2, a3, b0, b1);
                mma16(o[2*pn+1][0], o[2*pn+1][1], o[2*pn+1][2], o[2*pn+1][3],
                      a0, a1, a2, a3, b2, b3);
            }
        }
    }

    float inv_lo = 1.0f / l_lo;
    float inv_hi = 1.0f / l_hi;
    __half* Og = attn_out + (size_t)(b * SEQ + q0) * D_MODEL + h * HDIM;
    #pragma unroll
    for (int nt = 0; nt < 8; nt++) {
        int col = nt * 8 + 2 * ct;
        *(__half2*)&Og[(size_t)rl * D_MODEL + col] =
            __floats2half2_rn(o[nt][0] * inv_lo, o[nt][1] * inv_lo);
        *(__half2*)&Og[(size_t)(rl + 8) * D_MODEL + col] =
            __floats2half2_rn(o[nt][2] * inv_hi, o[nt][3] * inv_hi);
    }
}

// ===========================================================================
extern "C" void kernel_launch(void* const* d_in, const int* in_sizes, int n_in,
                              void* d_out, int out_size)
{
    const float* x      = (const float*)d_in[0];
    const float* w_qkv  = (const float*)d_in[1];
    const float* w_proj = (const float*)d_in[2];
    float* out = (float*)d_out;

    __half *qkvh, *attnh, *xh, *wqh, *wph;
    cudaGetSymbolAddress((void**)&qkvh,  g_qkvh);
    cudaGetSymbolAddress((void**)&attnh, g_attnh);
    cudaGetSymbolAddress((void**)&xh,    g_xh);
    cudaGetSymbolAddress((void**)&wqh,   g_wqh);
    cudaGetSymbolAddress((void**)&wph,   g_wph);

    cudaFuncSetAttribute(gemm_f16<__half>,
                         cudaFuncAttributeMaxDynamicSharedMemorySize, GEMM_SMEM);
    cudaFuncSetAttribute(gemm_f16<float>,
                         cudaFuncAttributeMaxDynamicSharedMemorySize, GEMM_SMEM);
    cudaFuncSetAttribute(attn_f16,
                         cudaFuncAttributeMaxDynamicSharedMemorySize, ATTN_SMEM);

    // 0) convert inputs/weights to fp16 (one launch)
    int n4 = N4X + N4Q + N4P;
    f2h_all<<<(n4 + 255) / 256, 256>>>(
        (const float4*)x, (const float4*)w_qkv, (const float4*)w_proj,
        (__half2*)xh, (__half2*)wqh, (__half2*)wph);

    // 1) QKV projection; Q columns pre-scaled by 1/8
    dim3 g1(QKVDIM/128, MROWS/128);
    gemm_f16<__half><<<g1, 256, GEMM_SMEM>>>(xh, wqh, qkvh,
                                             MROWS, QKVDIM, D_MODEL,
                                             D_MODEL, 0.125f);

    // 2) causal flash attention (P in registers)
    dim3 g2(SEQ/128, NHEAD, BATCH);
    attn_f16<<<g2, 256, ATTN_SMEM>>>(qkvh, attnh);

    // 3) output projection (fp16 in, fp32 out)
    dim3 g3(D_MODEL/128, MROWS/128);
    gemm_f16<float><<<g3, 256, GEMM_SMEM>>>(attnh, wph, out,
                                            MROWS, D_MODEL, D_MODEL,
                                            0, 1.0f);
}

// round 11
// speedup vs baseline: 1.9729x; 1.0147x over previous
#include <cuda_runtime.h>
#include <cuda_fp16.h>
#include <cstdint>

#define D_MODEL 1024
#define NHEAD   16
#define HDIM    64
#define BATCH   2
#define SEQ     2048
#define MROWS   (BATCH*SEQ)       // 4096
#define QKVDIM  (3*D_MODEL)       // 3072

// Scratch (no cudaMalloc allowed)
__device__ __half g_qkvh [BATCH*SEQ*QKVDIM];   // 25 MB
__device__ __half g_attnh[BATCH*SEQ*D_MODEL];  //  8 MB
__device__ __half g_xh   [MROWS*D_MODEL];      //  8 MB
__device__ __half g_wqh  [QKVDIM*D_MODEL];     //  6 MB
__device__ __half g_wph  [D_MODEL*D_MODEL];    //  2 MB

// ---------------------------------------------------------------------------
// helpers
// ---------------------------------------------------------------------------
static __device__ __forceinline__ uint32_t smem_u32(const void* p) {
    uint32_t a;
    asm("{ .reg .u64 t; cvta.to.shared.u64 t, %1; cvt.u32.u64 %0, t; }"
        : "=r"(a) : "l"(p));
    return a;
}
static __device__ __forceinline__ void mma16(
    float& c0, float& c1, float& c2, float& c3,
    uint32_t a0, uint32_t a1, uint32_t a2, uint32_t a3,
    uint32_t b0, uint32_t b1)
{
    asm volatile(
        "mma.sync.aligned.m16n8k16.row.col.f32.f16.f16.f32 "
        "{%0,%1,%2,%3}, {%4,%5,%6,%7}, {%8,%9}, {%0,%1,%2,%3};"
        : "+f"(c0), "+f"(c1), "+f"(c2), "+f"(c3)
        : "r"(a0), "r"(a1), "r"(a2), "r"(a3), "r"(b0), "r"(b1));
}
static __device__ __forceinline__ void ldmx4(
    uint32_t& r0, uint32_t& r1, uint32_t& r2, uint32_t& r3, uint32_t addr)
{
    asm volatile("ldmatrix.sync.aligned.m8n8.x4.shared.b16 {%0,%1,%2,%3}, [%4];"
                 : "=r"(r0), "=r"(r1), "=r"(r2), "=r"(r3) : "r"(addr));
}
static __device__ __forceinline__ void ldmx4t(
    uint32_t& r0, uint32_t& r1, uint32_t& r2, uint32_t& r3, uint32_t addr)
{
    asm volatile("ldmatrix.sync.aligned.m8n8.x4.trans.shared.b16 {%0,%1,%2,%3}, [%4];"
                 : "=r"(r0), "=r"(r1), "=r"(r2), "=r"(r3) : "r"(addr));
}
static __device__ __forceinline__ void cpa16(uint32_t dst, const void* src) {
    asm volatile("cp.async.ca.shared.global [%0], [%1], 16;"
                 :: "r"(dst), "l"(src) : "memory");
}
static __device__ __forceinline__ void cpa_commit() {
    asm volatile("cp.async.commit_group;" ::: "memory");
}
static __device__ __forceinline__ void cpa_wait1() {
    asm volatile("cp.async.wait_group 1;" ::: "memory");
}
static __device__ __forceinline__ void cpa_wait0() {
    asm volatile("cp.async.wait_group 0;" ::: "memory");
}
static __device__ __forceinline__ void st2h(__half* C, size_t off, float a, float b) {
    *(__half2*)(C + off) = __floats2half2_rn(a, b);
}
static __device__ __forceinline__ void st2h(float* C, size_t off, float a, float b) {
    *(float2*)(C + off) = make_float2(a, b);
}
static __device__ __forceinline__ uint32_t packh2(float a, float b) {
    __half2 h = __floats2half2_rn(a, b);
    return *(uint32_t*)&h;
}

// ---------------------------------------------------------------------------
// single-launch f32 -> f16 conversion of x, w_qkv, w_proj
// ---------------------------------------------------------------------------
#define N4X (MROWS*D_MODEL/4)
#define N4Q (QKVDIM*D_MODEL/4)
#define N4P (D_MODEL*D_MODEL/4)
__global__ void __launch_bounds__(256) f2h_all(
    const float4* __restrict__ x, const float4* __restrict__ wq,
    const float4* __restrict__ wp,
    __half2* __restrict__ xh, __half2* __restrict__ wqh, __half2* __restrict__ wph)
{
    int i = blockIdx.x * 256 + threadIdx.x;
    const float4* src; __half2* dst; int j;
    if (i < N4X)                { src = x;  dst = xh;  j = i; }
    else if (i < N4X + N4Q)     { src = wq; dst = wqh; j = i - N4X; }
    else if (i < N4X + N4Q + N4P){ src = wp; dst = wph; j = i - N4X - N4Q; }
    else return;
    float4 v = src[j];
    dst[2 * j]     = __floats2half2_rn(v.x, v.y);
    dst[2 * j + 1] = __floats2half2_rn(v.z, v.w);
}

// ===========================================================================
// fp16 mma GEMM (TN): unchanged structure (at the mma.sync issue ceiling).
// ===========================================================================
#define HSTAGE    32768
#define GEMM_SMEM (3*HSTAGE)

template<typename OutT>
__global__ void __launch_bounds__(256, 2) gemm_f16(
    const __half* __restrict__ A, const __half* __restrict__ B,
    OutT* __restrict__ C, int M, int N, int K, int q_cols, float qs)
{
    extern __shared__ char smh[];
    const uint32_t sbase = smem_u32(smh);

    const int tid  = threadIdx.x;
    const int wid  = tid >> 5;
    const int lane = tid & 31;
    const int g    = lane >> 2;
    const int ct   = lane & 3;
    const int wm   = wid & 1;
    const int wn   = wid >> 1;
    const int bm   = blockIdx.y * 128;
    const int bn   = blockIdx.x * 128;
    const float osc = (bn < q_cols) ? qs : 1.0f;

    const int l8 = lane & 7;
    const int h1 = (lane >> 3) & 1;
    const int h2 = lane >> 4;

    uint32_t arow[4], a7[4], brow[2], b7[2];
    #pragma unroll
    for (int mi = 0; mi < 4; mi++) {
        int r = wm * 64 + mi * 16 + l8 + h1 * 8;
        arow[mi] = (uint32_t)(r * 128);
        a7[mi]   = (uint32_t)(r & 7);
    }
    #pragma unroll
    for (int p = 0; p < 2; p++) {
        int r = wn * 32 + p * 16 + l8 + h2 * 8;
        brow[p] = 16384u + (uint32_t)(r * 128);
        b7[p]   = (uint32_t)(r & 7);
    }

    const int crow = tid >> 1;
    const int cc0  = (tid & 1) * 4;
    const __half* Ag = A + (size_t)(bm + crow) * K;
    const __half* Bg = B + (size_t)(bn + crow) * K;
    uint32_t dwa[4], dwb[4];
    #pragma unroll
    for (int i = 0; i < 4; i++) {
        uint32_t sw = (uint32_t)(((cc0 + i) ^ (crow & 7)) * 16);
        dwa[i] = (uint32_t)(crow * 128) + sw;
        dwb[i] = 16384u + (uint32_t)(crow * 128) + sw;
    }

    const int nkt = K / 64;

    float acc[4][4][4];
    #pragma unroll
    for (int i = 0; i < 4; i++)
        #pragma unroll
        for (int j = 0; j < 4; j++)
            #pragma unroll
            for (int e = 0; e < 4; e++) acc[i][j][e] = 0.f;

    #pragma unroll
    for (int s = 0; s < 2; s++) {
        uint32_t st = sbase + (uint32_t)s * HSTAGE;
        #pragma unroll
        for (int i = 0; i < 4; i++) {
            cpa16(st + dwa[i], Ag + s * 64 + (cc0 + i) * 8);
            cpa16(st + dwb[i], Bg + s * 64 + (cc0 + i) * 8);
        }
        cpa_commit();
    }

    int sc = 0;
    for (int kt = 0; kt < nkt; kt++) {
        cpa_wait1();
        __syncthreads();

        if (kt + 2 < nkt) {
            int sn = sc + 2; if (sn >= 3) sn -= 3;
            uint32_t st = sbase + (uint32_t)sn * HSTAGE;
            #pragma unroll
            for (int i = 0; i < 4; i++) {
                cpa16(st + dwa[i], Ag + (kt + 2) * 64 + (cc0 + i) * 8);
                cpa16(st + dwb[i], Bg + (kt + 2) * 64 + (cc0 + i) * 8);
            }
        }
        cpa_commit();

        const uint32_t cbase = sbase + (uint32_t)sc * HSTAGE;
        #pragma unroll
        for (int ks = 0; ks < 4; ks++) {
            uint32_t a[4][4], bb[2][4];
            #pragma unroll
            for (int mi = 0; mi < 4; mi++)
                ldmx4(a[mi][0], a[mi][1], a[mi][2], a[mi][3],
                      cbase + arow[mi] + ((((uint32_t)(ks * 2 + h2)) ^ a7[mi]) << 4));
            #pragma unroll
            for (int p = 0; p < 2; p++)
                ldmx4(bb[p][0], bb[p][1], bb[p][2], bb[p][3],
                      cbase + brow[p] + ((((uint32_t)(ks * 2 + h1)) ^ b7[p]) << 4));
            #pragma unroll
            for (int mi = 0; mi < 4; mi++)
                #pragma unroll
                for (int nt = 0; nt < 4; nt++)
                    mma16(acc[mi][nt][0], acc[mi][nt][1], acc[mi][nt][2], acc[mi][nt][3],
                          a[mi][0], a[mi][1], a[mi][2], a[mi][3],
                          bb[nt >> 1][(nt & 1) * 2], bb[nt >> 1][(nt & 1) * 2 + 1]);
        }
        sc++; if (sc >= 3) sc -= 3;
    }

    #pragma unroll
    for (int mi = 0; mi < 4; mi++) {
        int r0 = bm + wm * 64 + mi * 16 + g;
        #pragma unroll
        for (int nt = 0; nt < 4; nt++) {
            int c0 = bn + wn * 32 + nt * 8 + 2 * ct;
            st2h(C, (size_t)r0 * N + c0,
                 acc[mi][nt][0] * osc, acc[mi][nt][1] * osc);
            st2h(C, (size_t)(r0 + 8) * N + c0,
                 acc[mi][nt][2] * osc, acc[mi][nt][3] * osc);
        }
    }
}

// ===========================================================================
// Flash attention, fp16 mma, P in registers (FA2), exp2-domain softmax:
// Q pre-scaled by 0.125*log2(e) in the QKV GEMM epilogue, so S is already
// in log2 units -> p = exp2f(s - m), alpha = exp2f(m_old - m_new).
// Per-lane l partials; quad-reduce deferred to the epilogue.
// smem: Q 16K | K 2x8K | V 2x8K = 48K -> 2 CTAs/SM.
// ===========================================================================
#define AQ_OFF 0
#define AK_OFF 16384
#define AV_OFF 32768
#define ATTN_SMEM 49152

__global__ void __launch_bounds__(256, 2) attn_f16(
    const __half* __restrict__ qkv, __half* __restrict__ attn_out)
{
    extern __shared__ char smh[];
    const uint32_t sb = smem_u32(smh);

    const int qt  = (int)gridDim.x - 1 - (int)blockIdx.x;  // heavy blocks first
    const int h   = blockIdx.y;
    const int b   = blockIdx.z;
    const int tid = threadIdx.x;
    const int wid = tid >> 5;
    const int lane = tid & 31;
    const int g   = lane >> 2;
    const int ct  = lane & 3;
    const int q0  = qt * 128;
    const int rl  = wid * 16 + g;

    const int l8 = lane & 7;
    const int h1 = (lane >> 3) & 1;
    const int h2 = lane >> 4;

    const int arow = wid * 16 + l8 + h1 * 8;
    const uint32_t qbase = sb + AQ_OFF + (uint32_t)(arow * 128);
    const uint32_t a7 = (uint32_t)(arow & 7);
    uint32_t krow[4], k7[4];
    #pragma unroll
    for (int p = 0; p < 4; p++) {
        int r = p * 16 + l8 + h2 * 8;
        krow[p] = (uint32_t)(r * 128);
        k7[p]   = (uint32_t)(r & 7);
    }
    const int vr0 = l8 + h1 * 8;

    const size_t rs = QKVDIM;
    const __half* Qg = qkv + (size_t)b * SEQ * rs + h * HDIM;
    const __half* Kg = Qg + D_MODEL;
    const __half* Vg = Qg + 2 * D_MODEL;

    const int krr0 = tid >> 3;
    const int kc   = tid & 7;
    const uint32_t ksw0 = (uint32_t)(krr0 * 128 + ((kc ^ (krr0 & 7)) * 16));
    const int krr1 = krr0 + 32;
    const uint32_t ksw1 = (uint32_t)(krr1 * 128 + ((kc ^ (krr1 & 7)) * 16));

    // load Q tile (once)
    #pragma unroll
    for (int it = 0; it < 4; it++) {
        int idx = tid + it * 256;
        int rr  = idx >> 3;
        int c   = idx & 7;
        uint4 v = *(const uint4*)(Qg + (size_t)(q0 + rr) * rs + c * 8);
        *(uint4*)(smh + AQ_OFF + rr * 128 + ((c ^ (rr & 7)) * 16)) = v;
    }

    const int nkt = 2 * qt + 2;

    // prologue: kt=0 K/V into stage 0
    cpa16(sb + AK_OFF + ksw0, Kg + (size_t)krr0 * rs + kc * 8);
    cpa16(sb + AK_OFF + ksw1, Kg + (size_t)krr1 * rs + kc * 8);
    cpa16(sb + AV_OFF + ksw0, Vg + (size_t)krr0 * rs + kc * 8);
    cpa16(sb + AV_OFF + ksw1, Vg + (size_t)krr1 * rs + kc * 8);
    cpa_commit();

    float m_lo = -1e30f, m_hi = -1e30f, l_lo = 0.f, l_hi = 0.f;  // l per-lane
    float o[8][4];
    #pragma unroll
    for (int nt = 0; nt < 8; nt++)
        #pragma unroll
        for (int e = 0; e < 4; e++) o[nt][e] = 0.f;

    for (int kt = 0; kt < nkt; kt++) {
        cpa_wait0();
        __syncthreads();

        if (kt + 1 < nkt) {
            const int k1 = (kt + 1) * 64;
            const uint32_t so = (uint32_t)((kt + 1) & 1) * 8192u;
            cpa16(sb + AK_OFF + so + ksw0, Kg + (size_t)(k1 + krr0) * rs + kc * 8);
            cpa16(sb + AK_OFF + so + ksw1, Kg + (size_t)(k1 + krr1) * rs + kc * 8);
            cpa16(sb + AV_OFF + so + ksw0, Vg + (size_t)(k1 + krr0) * rs + kc * 8);
            cpa16(sb + AV_OFF + so + ksw1, Vg + (size_t)(k1 + krr1) * rs + kc * 8);
            cpa_commit();
        }

        const int k0 = kt * 64;
        if (k0 > q0 + wid * 16 + 15) continue;

        const uint32_t kb = sb + AK_OFF + (uint32_t)(kt & 1) * 8192u;
        const uint32_t vb = sb + AV_OFF + (uint32_t)(kt & 1) * 8192u;

        // ---- S = Q K^T  (S already in log2 units) ----
        float s[8][4];
        #pragma unroll
        for (int nt = 0; nt < 8; nt++)
            #pragma unroll
            for (int e = 0; e < 4; e++) s[nt][e] = 0.f;

        #pragma unroll
        for (int ks = 0; ks < 4; ks++) {
            uint32_t a0, a1, a2, a3;
            ldmx4(a0, a1, a2, a3, qbase + ((((uint32_t)(ks * 2 + h2)) ^ a7) << 4));
            #pragma unroll
            for (int p = 0; p < 4; p++) {
                uint32_t b0, b1, b2, b3;
                ldmx4(b0, b1, b2, b3, kb + krow[p] + ((((uint32_t)(ks * 2 + h1)) ^ k7[p]) << 4));
                mma16(s[2*p][0], s[2*p][1], s[2*p][2], s[2*p][3],
                      a0, a1, a2, a3, b0, b1);
                mma16(s[2*p+1][0], s[2*p+1][1], s[2*p+1][2], s[2*p+1][3],
                      a0, a1, a2, a3, b2, b3);
            }
        }

        // ---- causal mask ----
        const int rglo = q0 + rl;
        const int rghi = rglo + 8;
        if (k0 + 63 > rglo) {
            #pragma unroll
            for (int nt = 0; nt < 8; nt++) {
                int key = k0 + nt * 8 + 2 * ct;
                if (key     > rglo) s[nt][0] = -1e30f;
                if (key + 1 > rglo) s[nt][1] = -1e30f;
                if (key     > rghi) s[nt][2] = -1e30f;
                if (key + 1 > rghi) s[nt][3] = -1e30f;
            }
        }

        // ---- online softmax (base 2; quad reduce for m only) ----
        float tlo = -1e30f, thi = -1e30f;
        #pragma unroll
        for (int nt = 0; nt < 8; nt++) {
            tlo = fmaxf(tlo, fmaxf(s[nt][0], s[nt][1]));
            thi = fmaxf(thi, fmaxf(s[nt][2], s[nt][3]));
        }
        tlo = fmaxf(tlo, __shfl_xor_sync(0xffffffffu, tlo, 1));
        tlo = fmaxf(tlo, __shfl_xor_sync(0xffffffffu, tlo, 2));
        thi = fmaxf(thi, __shfl_xor_sync(0xffffffffu, thi, 1));
        thi = fmaxf(thi, __shfl_xor_sync(0xffffffffu, thi, 2));

        float mn_lo = fmaxf(m_lo, tlo);
        float mn_hi = fmaxf(m_hi, thi);
        float al_lo = exp2f(m_lo - mn_lo);
        float al_hi = exp2f(m_hi - mn_hi);
        m_lo = mn_lo; m_hi = mn_hi;

        // ---- exp2 + pack P into A-fragments; l stays per-lane ----
        uint32_t plo[8], phi[8];
        float ps_lo = 0.f, ps_hi = 0.f;
        #pragma unroll
        for (int nt = 0; nt < 8; nt++) {
            float p0 = exp2f(s[nt][0] - mn_lo);
            float p1 = exp2f(s[nt][1] - mn_lo);
            float p2 = exp2f(s[nt][2] - mn_hi);
            float p3 = exp2f(s[nt][3] - mn_hi);
            ps_lo += p0 + p1;
            ps_hi += p2 + p3;
            plo[nt] = packh2(p0, p1);
            phi[nt] = packh2(p2, p3);
        }
        l_lo = l_lo * al_lo + ps_lo;
        l_hi = l_hi * al_hi + ps_hi;

        #pragma unroll
        for (int nt = 0; nt < 8; nt++) {
            o[nt][0] *= al_lo; o[nt][1] *= al_lo;
            o[nt][2] *= al_hi; o[nt][3] *= al_hi;
        }

        // ---- O += P V (P from registers; V via ldmatrix.trans) ----
        #pragma unroll
        for (int ks = 0; ks < 4; ks++) {
            uint32_t a0 = plo[2*ks], a1 = phi[2*ks];
            uint32_t a2 = plo[2*ks+1], a3 = phi[2*ks+1];
            int vrow = ks * 16 + vr0;
            uint32_t vbase = vb + (uint32_t)(vrow * 128);
            uint32_t v7 = (uint32_t)(vrow & 7);
            #pragma unroll
            for (int pn = 0; pn < 4; pn++) {
                uint32_t b0, b1, b2, b3;
                ldmx4t(b0, b1, b2, b3, vbase + ((((uint32_t)(pn * 2 + h2)) ^ v7) << 4));
                mma16(o[2*pn][0], o[2*pn][1], o[2*pn][2], o[2*pn][3],
                      a0, a1, a2, a3, b0, b1);
                mma16(o[2*pn+1][0], o[2*pn+1][1], o[2*pn+1][2], o[2*pn+1][3],
                      a0, a1, a2, a3, b2, b3);
            }
        }
    }

    // final l reduction across the quad (deferred from the loop)
    l_lo += __shfl_xor_sync(0xffffffffu, l_lo, 1);
    l_lo += __shfl_xor_sync(0xffffffffu, l_lo, 2);
    l_hi += __shfl_xor_sync(0xffffffffu, l_hi, 1);
    l_hi += __shfl_xor_sync(0xffffffffu, l_hi, 2);
    float inv_lo = 1.0f / l_lo;
    float inv_hi = 1.0f / l_hi;

    __half* Og = attn_out + (size_t)(b * SEQ + q0) * D_MODEL + h * HDIM;
    #pragma unroll
    for (int nt = 0; nt < 8; nt++) {
        int col = nt * 8 + 2 * ct;
        *(__half2*)&Og[(size_t)rl * D_MODEL + col] =
            __floats2half2_rn(o[nt][0] * inv_lo, o[nt][1] * inv_lo);
        *(__half2*)&Og[(size_t)(rl + 8) * D_MODEL + col] =
            __floats2half2_rn(o[nt][2] * inv_hi, o[nt][3] * inv_hi);
    }
}

// ===========================================================================
extern "C" void kernel_launch(void* const* d_in, const int* in_sizes, int n_in,
                              void* d_out, int out_size)
{
    const float* x      = (const float*)d_in[0];
    const float* w_qkv  = (const float*)d_in[1];
    const float* w_proj = (const float*)d_in[2];
    float* out = (float*)d_out;

    __half *qkvh, *attnh, *xh, *wqh, *wph;
    cudaGetSymbolAddress((void**)&qkvh,  g_qkvh);
    cudaGetSymbolAddress((void**)&attnh, g_attnh);
    cudaGetSymbolAddress((void**)&xh,    g_xh);
    cudaGetSymbolAddress((void**)&wqh,   g_wqh);
    cudaGetSymbolAddress((void**)&wph,   g_wph);

    cudaFuncSetAttribute(gemm_f16<__half>,
                         cudaFuncAttributeMaxDynamicSharedMemorySize, GEMM_SMEM);
    cudaFuncSetAttribute(gemm_f16<float>,
                         cudaFuncAttributeMaxDynamicSharedMemorySize, GEMM_SMEM);
    cudaFuncSetAttribute(attn_f16,
                         cudaFuncAttributeMaxDynamicSharedMemorySize, ATTN_SMEM);

    // 0) convert inputs/weights to fp16 (one launch)
    int n4 = N4X + N4Q + N4P;
    f2h_all<<<(n4 + 255) / 256, 256>>>(
        (const float4*)x, (const float4*)w_qkv, (const float4*)w_proj,
        (__half2*)xh, (__half2*)wqh, (__half2*)wph);

    // 1) QKV projection; Q columns pre-scaled by (1/8)*log2(e)
    dim3 g1(QKVDIM/128, MROWS/128);
    gemm_f16<__half><<<g1, 256, GEMM_SMEM>>>(xh, wqh, qkvh,
                                             MROWS, QKVDIM, D_MODEL,
                                             D_MODEL, 0.125f * 1.44269504f);

    // 2) causal flash attention (P in registers, exp2 softmax)
    dim3 g2(SEQ/128, NHEAD, BATCH);
    attn_f16<<<g2, 256, ATTN_SMEM>>>(qkvh, attnh);

    // 3) output projection (fp16 in, fp32 out)
    dim3 g3(D_MODEL/128, MROWS/128);
    gemm_f16<float><<<g3, 256, GEMM_SMEM>>>(attnh, wph, out,
                                            MROWS, D_MODEL, D_MODEL,
                                            0, 1.0f);
}